// round 9
// baseline (speedup 1.0000x reference)
#include <cuda_runtime.h>
#include <cuda_bf16.h>
#include <math.h>
#include <cstdint>

// ---------------------------------------------------------------------------
// Problem constants: B=2, L=2048, D=2048, H=16, dk=64, dv=128.  M = B*L = 4096.
// ---------------------------------------------------------------------------
#define MTOK 4096
#define DMODEL 2048
#define DQK 1024
#define NHEAD 16
#define DK 64
#define DV 128
#define SEQ 2048
#define SCALE_K 0.08838834764831845f   // 128^-0.5
#define INV_NORM 0.0625f               // 1/16

// tcgen05 / f32x2 only exist in the arch-specific (sm_103a) compilation pass.
#if defined(__CUDA_ARCH__) && (__CUDA_ARCH__ == 1030) && defined(__CUDA_ARCH_FEAT_SM103_ALL)
#define USE_TCGEN05 1
#else
#define USE_TCGEN05 0
#endif

// ---------------------------------------------------------------------------
// Scratch (device globals: no allocation allowed)
// ---------------------------------------------------------------------------
__device__ float g_q [MTOK * DQK];
__device__ float g_k [MTOK * DQK];
__device__ float g_kg[MTOK * DQK];
__device__ float g_v [MTOK * DMODEL];
__device__ float g_gp[MTOK * DMODEL];
__device__ float g_o [MTOK * DMODEL];

__device__ __nv_bfloat16 g_xh[MTOK * DMODEL],   g_xl[MTOK * DMODEL];
__device__ __nv_bfloat16 g_zh[MTOK * DMODEL],   g_zl[MTOK * DMODEL];
__device__ __nv_bfloat16 g_wqh[DQK * DMODEL],   g_wql[DQK * DMODEL];
__device__ __nv_bfloat16 g_wkh[DQK * DMODEL],   g_wkl[DQK * DMODEL];
__device__ __nv_bfloat16 g_weh[DQK * DMODEL],   g_wel[DQK * DMODEL];   // Wkg2@Wkg1
__device__ __nv_bfloat16 g_wvh[DMODEL * DMODEL], g_wvl[DMODEL * DMODEL];
__device__ __nv_bfloat16 g_wgh[DMODEL * DMODEL], g_wgl[DMODEL * DMODEL];
__device__ __nv_bfloat16 g_woh[DMODEL * DMODEL], g_wol[DMODEL * DMODEL];

// ---------------------------------------------------------------------------
// PTX helpers
// ---------------------------------------------------------------------------
__device__ __forceinline__ uint32_t smem_u32(const void* p) {
    uint32_t a;
    asm("{ .reg .u64 t; cvta.to.shared.u64 t, %1; cvt.u32.u64 %0, t; }" : "=r"(a) : "l"(p));
    return a;
}

#define SWZ(o) ((o) ^ (((o) >> 3) & 0x70))

#define CP_ASYNC16(dst, src) \
    asm volatile("cp.async.cg.shared.global [%0], [%1], 16;" :: "r"(dst), "l"(src))
// Arrive-on-complete of ALL prior cp.async by this thread; .noinc counts
// against the barrier's initialized expected-arrival count (pipeline idiom).
#define CP_ASYNC_MBAR_ARRIVE(mb) \
    asm volatile("cp.async.mbarrier.arrive.noinc.shared.b64 [%0];" :: "r"((uint32_t)(mb)) : "memory")
#define CP_ASYNC_COMMIT() \
    asm volatile("cp.async.commit_group;" ::: "memory")
#define CP_ASYNC_WAIT(n) \
    asm volatile("cp.async.wait_group %0;" :: "n"(n) : "memory")

#define MBARRIER_INIT(mb, cnt) \
    asm volatile("mbarrier.init.shared.b64 [%0], %1;" :: "r"((uint32_t)(mb)), "r"((uint32_t)(cnt)) : "memory")

#define MBARRIER_WAIT_PARITY(mb, par) do { \
    uint32_t _mb = (uint32_t)(mb); uint32_t _p = (uint32_t)(par); uint32_t _done; \
    asm volatile("{\n\t.reg .pred p;\n\t" \
        "mbarrier.try_wait.parity.acquire.cta.shared::cta.b64 p, [%1], %2;\n\t" \
        "selp.b32 %0, 1, 0, p;\n\t}" : "=r"(_done) : "r"(_mb), "r"(_p) : "memory"); \
    if (!_done) { \
        asm volatile("{\n\t.reg .pred P1;\n\t" \
            "WL_%=:\n\t" \
            "mbarrier.try_wait.parity.acquire.cta.shared::cta.b64 P1, [%0], %1, 0x989680;\n\t" \
            "@P1 bra.uni WD_%=;\n\t" \
            "bra.uni WL_%=;\n\t" \
            "WD_%=:\n\t}" :: "r"(_mb), "r"(_p) : "memory"); \
    } \
} while (0)

#if USE_TCGEN05
__device__ __forceinline__ uint32_t elect_one_pred() {
    uint32_t pred;
    asm volatile("{\n\t.reg .pred p;\n\telect.sync _|p, 0xFFFFFFFF;\n\t"
                 "selp.b32 %0, 1, 0, p;\n\t}" : "=r"(pred));
    return pred;
}

#define TCGEN05_ALLOC(smem_res, ncols) \
    asm volatile("tcgen05.alloc.cta_group::1.sync.aligned.shared::cta.b32 [%0], %1;" \
                 :: "r"((uint32_t)(smem_res)), "r"((uint32_t)(ncols)) : "memory")
#define TCGEN05_DEALLOC(tm, ncols) \
    asm volatile("tcgen05.dealloc.cta_group::1.sync.aligned.b32 %0, %1;" :: "r"(tm), "r"((uint32_t)(ncols)))
#define TCGEN05_RELINQ() \
    asm volatile("tcgen05.relinquish_alloc_permit.cta_group::1.sync.aligned;")
#define TCGEN05_COMMIT(mb) \
    asm volatile("tcgen05.commit.cta_group::1.mbarrier::arrive::one.shared::cluster.b64 [%0];" \
                 :: "r"((uint32_t)(mb)) : "memory")
#define TCGEN05_FENCE_AFTER() \
    asm volatile("tcgen05.fence::after_thread_sync;" ::: "memory")
#define TCGEN05_WAIT_LD() \
    asm volatile("tcgen05.wait::ld.sync.aligned;" ::: "memory")
#define FENCE_PROXY_ASYNC() \
    asm volatile("fence.proxy.async.shared::cta;" ::: "memory")

#define TCGEN05_LD_X32(r, tm) \
    asm volatile("tcgen05.ld.sync.aligned.32x32b.x32.b32 " \
        "{%0, %1, %2, %3, %4, %5, %6, %7, %8, %9, %10, %11, %12, %13, %14, %15, " \
        " %16, %17, %18, %19, %20, %21, %22, %23, %24, %25, %26, %27, %28, %29, %30, %31}, [%32];" \
        : "=r"((r)[0]),  "=r"((r)[1]),  "=r"((r)[2]),  "=r"((r)[3]), \
          "=r"((r)[4]),  "=r"((r)[5]),  "=r"((r)[6]),  "=r"((r)[7]), \
          "=r"((r)[8]),  "=r"((r)[9]),  "=r"((r)[10]), "=r"((r)[11]), \
          "=r"((r)[12]), "=r"((r)[13]), "=r"((r)[14]), "=r"((r)[15]), \
          "=r"((r)[16]), "=r"((r)[17]), "=r"((r)[18]), "=r"((r)[19]), \
          "=r"((r)[20]), "=r"((r)[21]), "=r"((r)[22]), "=r"((r)[23]), \
          "=r"((r)[24]), "=r"((r)[25]), "=r"((r)[26]), "=r"((r)[27]), \
          "=r"((r)[28]), "=r"((r)[29]), "=r"((r)[30]), "=r"((r)[31]) \
        : "r"(tm))

// K-major SW128 descriptor: layout=2 (SW128), version=1, SBO=64, LBO=1
static constexpr uint64_t DESC_BASE_SW128 =
    (uint64_t(2) << 61) | (uint64_t(1) << 46) | (uint64_t(64) << 32) | (uint64_t(1) << 16);
#define MAKE_DESC(addr) (DESC_BASE_SW128 | ((uint64_t)((addr) >> 4) & 0x3FFF))

__device__ __forceinline__ void mma_f16_ss(uint32_t d, uint64_t ad, uint64_t bd,
                                           uint32_t idesc, uint32_t en) {
    asm volatile("{\n\t.reg .pred p;\n\tsetp.ne.u32 p, %5, 0;\n\t"
        "tcgen05.mma.cta_group::1.kind::f16 [%0], %1, %2, %3, {%4, %4, %4, %4}, p;\n\t}"
        :: "r"(d), "l"(ad), "l"(bd), "r"(idesc), "r"(0u), "r"(en) : "memory");
}

// ---- packed fp32x2 (sm_103a): 2 IEEE fp32 lanes per instruction ----
__device__ __forceinline__ unsigned long long fma2(unsigned long long a,
                                                   unsigned long long b,
                                                   unsigned long long c) {
    unsigned long long d;
    asm("fma.rn.f32x2 %0, %1, %2, %3;" : "=l"(d) : "l"(a), "l"(b), "l"(c));
    return d;
}
__device__ __forceinline__ unsigned long long mul2(unsigned long long a,
                                                   unsigned long long b) {
    unsigned long long d;
    asm("mul.rn.f32x2 %0, %1, %2;" : "=l"(d) : "l"(a), "l"(b));
    return d;
}
__device__ __forceinline__ unsigned long long add2(unsigned long long a,
                                                   unsigned long long b) {
    unsigned long long d;
    asm("add.rn.f32x2 %0, %1, %2;" : "=l"(d) : "l"(a), "l"(b));
    return d;
}
__device__ __forceinline__ unsigned long long dup2(float x) {
    unsigned long long d;
    asm("mov.b64 %0, {%1, %1};" : "=l"(d) : "f"(x));
    return d;
}
__device__ __forceinline__ float hsum2(unsigned long long p) {
    float lo, hi;
    asm("mov.b64 {%0, %1}, %2;" : "=f"(lo), "=f"(hi) : "l"(p));
    return lo + hi;
}
#else
// HMMA fallback primitive: m16n8k16 row.col bf16 -> f32
__device__ __forceinline__ void mma16816(float* d, const uint32_t* a, const uint32_t* b) {
    asm volatile("mma.sync.aligned.m16n8k16.row.col.f32.bf16.bf16.f32 "
        "{%0,%1,%2,%3}, {%4,%5,%6,%7}, {%8,%9}, {%0,%1,%2,%3};"
        : "+f"(d[0]), "+f"(d[1]), "+f"(d[2]), "+f"(d[3])
        : "r"(a[0]), "r"(a[1]), "r"(a[2]), "r"(a[3]), "r"(b[0]), "r"(b[1]));
}
#endif

// ---------------------------------------------------------------------------
// bf16x3 GEMM:  C[M,N] = alpha * (A @ B^T) (+ bias), split hi/lo operands.
// Tile 128x256 (two N=128 MMA halves), K-chunk 64, WARP-SPECIALIZED.
// ---------------------------------------------------------------------------
#define BUFB 98304
#define GEMM_DSM (2 * BUFB + 1024)
#define GEMM_THREADS 288

__global__ __launch_bounds__(GEMM_THREADS) __cluster_dims__(1, 1, 1)
void gemm3(const __nv_bfloat16* __restrict__ Ah, const __nv_bfloat16* __restrict__ Al,
           const __nv_bfloat16* __restrict__ Bh, const __nv_bfloat16* __restrict__ Bl,
           const float* __restrict__ bias, float* __restrict__ C,
           int N, int K, float alpha)
{
    extern __shared__ char dsm[];

    const int tid = threadIdx.x;
    const int bm = blockIdx.y * 128;
    const int bn = blockIdx.x * 256;

    const uint32_t raw = smem_u32(dsm);
    const uint32_t sbase = (raw + 1023u) & ~1023u;
    char* sgen = dsm + (sbase - raw);

    const int NC = K / 64;

#if USE_TCGEN05
    __shared__ uint32_t s_tmem;
    __shared__ __align__(16) uint64_t s_full[2];
    __shared__ __align__(16) uint64_t s_empty[2];
    const uint32_t full0  = smem_u32(&s_full[0]),  full1  = smem_u32(&s_full[1]);
    const uint32_t empty0 = smem_u32(&s_empty[0]), empty1 = smem_u32(&s_empty[1]);

    if (tid < 32) { TCGEN05_ALLOC(smem_u32(&s_tmem), 256); TCGEN05_RELINQ(); }
    if (tid == 0) {
        MBARRIER_INIT(full0, 256);  MBARRIER_INIT(full1, 256);
        MBARRIER_INIT(empty0, 1);   MBARRIER_INIT(empty1, 1);
    }
    __syncthreads();
    const uint32_t tmem = s_tmem;

    if (tid < 256) {
        // ---------------- loader role ----------------
        const int lr  = tid >> 3;          // 0..31 base row
        const int seg = tid & 7;           // 16B segment within 128B row
        for (int c = 0; c < NC; c++) {
            if (c >= 2)
                MBARRIER_WAIT_PARITY((c & 1) ? empty1 : empty0, ((c - 2) >> 1) & 1);
            const uint32_t bb = sbase + (c & 1) * BUFB;
            const int k0 = c * 64;
#pragma unroll
            for (int t2 = 0; t2 < 2; t2++) {               // Ah, Al (128 rows)
                const __nv_bfloat16* basep = t2 ? Al : Ah;
                uint32_t tb = bb + t2 * 16384;
#pragma unroll
                for (int ii = 0; ii < 4; ii++) {
                    int r = lr + ii * 32;
                    const void* src = basep + (size_t)(bm + r) * K + k0 + seg * 8;
                    CP_ASYNC16(tb + SWZ((uint32_t)(r * 128 + seg * 16)), src);
                }
            }
#pragma unroll
            for (int t2 = 0; t2 < 2; t2++) {               // Bh, Bl (256 rows)
                const __nv_bfloat16* basep = t2 ? Bl : Bh;
                uint32_t tb = bb + 32768 + t2 * 32768;
#pragma unroll
                for (int ii = 0; ii < 8; ii++) {
                    int r = lr + ii * 32;
                    const void* src = basep + (size_t)(bn + r) * K + k0 + seg * 8;
                    CP_ASYNC16(tb + SWZ((uint32_t)(r * 128 + seg * 16)), src);
                }
            }
            CP_ASYNC_MBAR_ARRIVE((c & 1) ? full1 : full0);
        }
    } else if (elect_one_pred()) {
        // ---------------- MMA role (single elected thread of warp 8) --------
        const uint32_t IDESC = (1u << 4) | (1u << 7) | (1u << 10) | (16u << 17) | (8u << 24);
        for (int c = 0; c < NC; c++) {
            MBARRIER_WAIT_PARITY((c & 1) ? full1 : full0, (c >> 1) & 1);
            FENCE_PROXY_ASYNC();           // generic (cp.async) -> async proxy
            const uint32_t ab = sbase + (c & 1) * BUFB;
            const uint64_t dAh  = MAKE_DESC(ab);
            const uint64_t dAl  = MAKE_DESC(ab + 16384);
            const uint64_t dBh0 = MAKE_DESC(ab + 32768);
            const uint64_t dBh1 = MAKE_DESC(ab + 32768 + 16384);
            const uint64_t dBl0 = MAKE_DESC(ab + 65536);
            const uint64_t dBl1 = MAKE_DESC(ab + 65536 + 16384);
            const uint32_t en0 = (c > 0);
#pragma unroll
            for (int ks = 0; ks < 4; ks++)
                mma_f16_ss(tmem,       dAh + ks * 2, dBh0 + ks * 2, IDESC, en0 || (ks > 0));
#pragma unroll
            for (int ks = 0; ks < 4; ks++)
                mma_f16_ss(tmem + 128, dAh + ks * 2, dBh1 + ks * 2, IDESC, en0 || (ks > 0));
#pragma unroll
            for (int ks = 0; ks < 4; ks++) {
                mma_f16_ss(tmem,       dAh + ks * 2, dBl0 + ks * 2, IDESC, 1u);
                mma_f16_ss(tmem + 128, dAh + ks * 2, dBl1 + ks * 2, IDESC, 1u);
                mma_f16_ss(tmem,       dAl + ks * 2, dBh0 + ks * 2, IDESC, 1u);
                mma_f16_ss(tmem + 128, dAl + ks * 2, dBh1 + ks * 2, IDESC, 1u);
            }
            TCGEN05_COMMIT((c & 1) ? empty1 : empty0);
        }
    }

    __syncthreads();
    // final MMA chunk NC-1: completion #((NC-1)>>1) on empty[(NC-1)&1]
    MBARRIER_WAIT_PARITY(((NC - 1) & 1) ? empty1 : empty0, ((NC - 1) >> 1) & 1);
    TCGEN05_FENCE_AFTER();
    __syncthreads();

    // epilogue: TMEM -> regs -> padded SMEM stage -> coalesced STG (8 slabs)
    float* stage = (float*)sgen;
    for (int slab = 0; slab < 8; slab++) {
        if (tid < 128) {
            uint32_t regs[32];
            TCGEN05_LD_X32(regs, tmem + slab * 32);
            TCGEN05_WAIT_LD();
#pragma unroll
            for (int cc = 0; cc < 32; cc++) stage[tid * 33 + cc] = __uint_as_float(regs[cc]);
        }
        __syncthreads();
        for (int e = tid; e < 4096; e += GEMM_THREADS) {
            int row = e >> 5, col = e & 31;
            float vv = stage[row * 33 + col] * alpha;
            if (bias) vv += bias[bn + slab * 32 + col];
            C[(size_t)(bm + row) * N + bn + slab * 32 + col] = vv;
        }
        __syncthreads();
    }
    if (tid < 32) TCGEN05_DEALLOC(tmem, 256);

#else  // ------------------- HMMA mma.sync fallback ------------------------
    const int warp = tid >> 5;
    const int lane = tid & 31;
    if (warp < 8) {
        const int wm = (warp & 3) * 32;
        const int wn = (warp >> 2) * 64;
        const int lg = lane >> 2;
        const int lt = lane & 3;
        const int lr  = tid >> 3;
        const int seg = tid & 7;

        auto load_chunk = [&](int c) {
            uint32_t bb = sbase + (c & 1) * BUFB;
            const int k0 = c * 64;
#pragma unroll
            for (int t2 = 0; t2 < 2; t2++) {
                const __nv_bfloat16* basep = t2 ? Al : Ah;
                uint32_t tb = bb + t2 * 16384;
#pragma unroll
                for (int ii = 0; ii < 4; ii++) {
                    int r = lr + ii * 32;
                    const void* src = basep + (size_t)(bm + r) * K + k0 + seg * 8;
                    CP_ASYNC16(tb + SWZ((uint32_t)(r * 128 + seg * 16)), src);
                }
            }
#pragma unroll
            for (int t2 = 0; t2 < 2; t2++) {
                const __nv_bfloat16* basep = t2 ? Bl : Bh;
                uint32_t tb = bb + 32768 + t2 * 32768;
#pragma unroll
                for (int ii = 0; ii < 8; ii++) {
                    int r = lr + ii * 32;
                    const void* src = basep + (size_t)(bn + r) * K + k0 + seg * 8;
                    CP_ASYNC16(tb + SWZ((uint32_t)(r * 128 + seg * 16)), src);
                }
            }
            CP_ASYNC_COMMIT();
        };

        for (int nh = 0; nh < 2; nh++) {
            float acc[2][8][4];
#pragma unroll
            for (int mt = 0; mt < 2; mt++)
#pragma unroll
                for (int nt = 0; nt < 8; nt++)
#pragma unroll
                    for (int r = 0; r < 4; r++) acc[mt][nt][r] = 0.f;

            load_chunk(0);
            for (int c = 0; c < NC; c++) {
                if (c + 1 < NC) { load_chunk(c + 1); CP_ASYNC_WAIT(1); }
                else            { CP_ASYNC_WAIT(0); }
                asm volatile("bar.sync 1, 256;" ::: "memory");

                char* bb = sgen + (c & 1) * BUFB;
                char* tAh = bb, *tAl = bb + 16384;
                char* tBh = bb + 32768 + nh * 16384, *tBl = bb + 65536 + nh * 16384;
#pragma unroll
                for (int kk = 0; kk < 64; kk += 16) {
                    const uint32_t kbase = (kk + lt * 2) * 2;
                    uint32_t bh[8][2], bl[8][2];
#pragma unroll
                    for (int nt = 0; nt < 8; nt++) {
                        uint32_t off = (uint32_t)((wn + nt * 8 + lg) * 128) + kbase;
                        bh[nt][0] = *(const uint32_t*)(tBh + SWZ(off));
                        bh[nt][1] = *(const uint32_t*)(tBh + SWZ(off + 16));
                        bl[nt][0] = *(const uint32_t*)(tBl + SWZ(off));
                        bl[nt][1] = *(const uint32_t*)(tBl + SWZ(off + 16));
                    }
#pragma unroll
                    for (int mt = 0; mt < 2; mt++) {
                        uint32_t o0 = (uint32_t)((wm + mt * 16 + lg) * 128) + kbase;
                        uint32_t o8 = o0 + 8 * 128;
                        uint32_t ah[4] = {
                            *(const uint32_t*)(tAh + SWZ(o0)),      *(const uint32_t*)(tAh + SWZ(o8)),
                            *(const uint32_t*)(tAh + SWZ(o0 + 16)), *(const uint32_t*)(tAh + SWZ(o8 + 16)) };
                        uint32_t al[4] = {
                            *(const uint32_t*)(tAl + SWZ(o0)),      *(const uint32_t*)(tAl + SWZ(o8)),
                            *(const uint32_t*)(tAl + SWZ(o0 + 16)), *(const uint32_t*)(tAl + SWZ(o8 + 16)) };
#pragma unroll
                        for (int nt = 0; nt < 8; nt++) mma16816(acc[mt][nt], ah, bh[nt]);
#pragma unroll
                        for (int nt = 0; nt < 8; nt++) mma16816(acc[mt][nt], ah, bl[nt]);
#pragma unroll
                        for (int nt = 0; nt < 8; nt++) mma16816(acc[mt][nt], al, bh[nt]);
                    }
                }
                asm volatile("bar.sync 1, 256;" ::: "memory");
            }
#pragma unroll
            for (int mt = 0; mt < 2; mt++) {
#pragma unroll
                for (int nt = 0; nt < 8; nt++) {
                    int row = bm + wm + mt * 16 + lg;
                    int col = bn + nh * 128 + wn + nt * 8 + lt * 2;
                    float b0 = bias ? bias[col]     : 0.f;
                    float b1 = bias ? bias[col + 1] : 0.f;
                    float2 v0 = { acc[mt][nt][0] * alpha + b0, acc[mt][nt][1] * alpha + b1 };
                    float2 v1 = { acc[mt][nt][2] * alpha + b0, acc[mt][nt][3] * alpha + b1 };
                    *(float2*)(C + (size_t)row * N + col)       = v0;
                    *(float2*)(C + (size_t)(row + 8) * N + col) = v1;
                }
            }
            asm volatile("bar.sync 1, 256;" ::: "memory");
        }
    }
#endif
}

// ---------------------------------------------------------------------------
// fp32 -> (hi, lo) bf16 split, vectorized by 4
// ---------------------------------------------------------------------------
__device__ __forceinline__ void split4(const float4 v,
                                       __nv_bfloat16* hi, __nv_bfloat16* lo, int i)
{
    __nv_bfloat16 h0 = __float2bfloat16(v.x), h1 = __float2bfloat16(v.y);
    __nv_bfloat16 h2 = __float2bfloat16(v.z), h3 = __float2bfloat16(v.w);
    __nv_bfloat16 l0 = __float2bfloat16(v.x - __bfloat162float(h0));
    __nv_bfloat16 l1 = __float2bfloat16(v.y - __bfloat162float(h1));
    __nv_bfloat16 l2 = __float2bfloat16(v.z - __bfloat162float(h2));
    __nv_bfloat16 l3 = __float2bfloat16(v.w - __bfloat162float(h3));
    ushort4 ph = { __bfloat16_as_ushort(h0), __bfloat16_as_ushort(h1),
                   __bfloat16_as_ushort(h2), __bfloat16_as_ushort(h3) };
    ushort4 pl = { __bfloat16_as_ushort(l0), __bfloat16_as_ushort(l1),
                   __bfloat16_as_ushort(l2), __bfloat16_as_ushort(l3) };
    ((ushort4*)hi)[i] = ph;
    ((ushort4*)lo)[i] = pl;
}

__global__ __launch_bounds__(256)
void split32(const float* __restrict__ s, __nv_bfloat16* __restrict__ hi,
             __nv_bfloat16* __restrict__ lo)
{
    int i = blockIdx.x * blockDim.x + threadIdx.x;
    split4(((const float4*)s)[i], hi, lo, i);
}

// One launch splitting all five weight matrices.
__global__ __launch_bounds__(256)
void split_w(const float* __restrict__ Wq, const float* __restrict__ Wk,
             const float* __restrict__ Wv, const float* __restrict__ Wg,
             const float* __restrict__ Wo,
             __nv_bfloat16* __restrict__ wqh, __nv_bfloat16* __restrict__ wql,
             __nv_bfloat16* __restrict__ wkh, __nv_bfloat16* __restrict__ wkl,
             __nv_bfloat16* __restrict__ wvh, __nv_bfloat16* __restrict__ wvl,
             __nv_bfloat16* __restrict__ wgh, __nv_bfloat16* __restrict__ wgl,
             __nv_bfloat16* __restrict__ woh, __nv_bfloat16* __restrict__ wol)
{
    int b = blockIdx.x;
    const float* src; __nv_bfloat16 *hi, *lo;
    if      (b < 2048)  { src = Wq; hi = wqh; lo = wql; }
    else if (b < 4096)  { src = Wk; hi = wkh; lo = wkl; b -= 2048; }
    else if (b < 8192)  { src = Wv; hi = wvh; lo = wvl; b -= 4096; }
    else if (b < 12288) { src = Wg; hi = wgh; lo = wgl; b -= 8192; }
    else                { src = Wo; hi = woh; lo = wol; b -= 12288; }
    int i = b * 256 + threadIdx.x;
    split4(((const float4*)src)[i], hi, lo, i);
}

// ---------------------------------------------------------------------------
// W_eff = Wkg2 @ Wkg1  ([1024,16] @ [16,2048] -> [1024,2048]), fused hi/lo split.
// ---------------------------------------------------------------------------
__global__ __launch_bounds__(256)
void weff_split(const float* __restrict__ W1,   // Wkg1 [16, 2048]
                const float* __restrict__ W2,   // Wkg2 [1024, 16]
                __nv_bfloat16* __restrict__ weh, __nv_bfloat16* __restrict__ wel)
{
    __shared__ __align__(16) float s1[16][128];
    const int tid = threadIdx.x;
    const int d0  = blockIdx.x * 128;
    const int n0  = blockIdx.y * 256;

#pragma unroll
    for (int it = 0; it < 2; it++) {
        int i = it * 256 + tid;
        int r = i >> 5, c4 = i & 31;
        *(float4*)&s1[r][c4 * 4] = *(const float4*)(W1 + r * DMODEL + d0 + c4 * 4);
    }
    __syncthreads();

    const int d4 = tid & 31;
    const int nb = tid >> 5;
    for (int n = n0 + nb; n < n0 + 256; n += 8) {
        const float4 w2a = *(const float4*)(W2 + n * 16);
        const float4 w2b = *(const float4*)(W2 + n * 16 + 4);
        const float4 w2c = *(const float4*)(W2 + n * 16 + 8);
        const float4 w2d = *(const float4*)(W2 + n * 16 + 12);
        float w2[16] = { w2a.x, w2a.y, w2a.z, w2a.w, w2b.x, w2b.y, w2b.z, w2b.w,
                         w2c.x, w2c.y, w2c.z, w2c.w, w2d.x, w2d.y, w2d.z, w2d.w };
        float4 acc = {0.f, 0.f, 0.f, 0.f};
#pragma unroll
        for (int r = 0; r < 16; r++) {
            float4 v = *(const float4*)&s1[r][d4 * 4];
            acc.x = fmaf(w2[r], v.x, acc.x);
            acc.y = fmaf(w2[r], v.y, acc.y);
            acc.z = fmaf(w2[r], v.z, acc.z);
            acc.w = fmaf(w2[r], v.w, acc.w);
        }
        split4(acc, weh, wel, n * (DMODEL / 4) + (d0 >> 2) + d4);
    }
}

// ---------------------------------------------------------------------------
// GLA recurrence. 256 blocks = B * H * 8 dv-chunks of 16; 128 threads.
// Inner loop uses packed fma.rn.f32x2 (sm_103a): 12 packed FMA = 24 MACs.
// ---------------------------------------------------------------------------
#define TT 16
__global__ __launch_bounds__(128)
void gla_rec(const float* __restrict__ q, const float* __restrict__ k,
             const float* __restrict__ kg, const float* __restrict__ v,
             float* __restrict__ o)
{
    const int blk   = blockIdx.x;       // 256 = B * H * 8
    const int chunk = blk & 7;
    const int head  = (blk >> 3) & 15;
    const int b     = blk >> 7;
    const int j0    = chunk * 16;

    const int tid = threadIdx.x;
    const int j   = tid >> 3;           // 0..15
    const int ig  = tid & 7;            // 0..7

    __shared__ __align__(16) float qs[TT][DK];
    __shared__ __align__(16) float ks[TT][DK];
    __shared__ __align__(16) float es[TT][DK];
    __shared__ __align__(16) float vs[TT][16];

    const float* qb = q  + (size_t)b * SEQ * DQK    + head * DK;
    const float* kb = k  + (size_t)b * SEQ * DQK    + head * DK;
    const float* gb = kg + (size_t)b * SEQ * DQK    + head * DK;
    const float* vb = v  + (size_t)b * SEQ * DMODEL + head * DV + j0;
    float*       ob = o  + (size_t)b * SEQ * DMODEL + head * DV + j0;

#if USE_TCGEN05
    unsigned long long S01 = 0ull, S23 = 0ull, S45 = 0ull, S67 = 0ull;
#else
    float S[8] = {0.f, 0.f, 0.f, 0.f, 0.f, 0.f, 0.f, 0.f};
#endif

    for (int t0 = 0; t0 < SEQ; t0 += TT) {
        // q/k/g: TT*64 floats = 256 float4 over 128 threads (2 each)
#pragma unroll
        for (int it = 0; it < 2; it++) {
            int idx = it * 128 + tid;
            int row = idx >> 4, c4 = idx & 15;
            size_t r4 = (size_t)(t0 + row) * (DQK / 4) + c4;
            float4 qv = ((const float4*)qb)[r4];
            float4 kv = ((const float4*)kb)[r4];
            float4 gv = ((const float4*)gb)[r4];
            *(float4*)&qs[row][c4 * 4] = qv;
            *(float4*)&ks[row][c4 * 4] = kv;
            float4 ev;
            float a0 = fminf(gv.x, 0.f) - log1pf(__expf(-fabsf(gv.x)));
            float a1 = fminf(gv.y, 0.f) - log1pf(__expf(-fabsf(gv.y)));
            float a2 = fminf(gv.z, 0.f) - log1pf(__expf(-fabsf(gv.z)));
            float a3 = fminf(gv.w, 0.f) - log1pf(__expf(-fabsf(gv.w)));
            ev.x = __expf(a0 * INV_NORM); ev.y = __expf(a1 * INV_NORM);
            ev.z = __expf(a2 * INV_NORM); ev.w = __expf(a3 * INV_NORM);
            *(float4*)&es[row][c4 * 4] = ev;
        }
        // v: TT*16 floats = 64 float4 (first 64 threads)
        if (tid < 64) {
            int row = tid >> 2, c4 = tid & 3;
            float4 vv = ((const float4*)vb)[(size_t)(t0 + row) * (DMODEL / 4) + c4];
            *(float4*)&vs[row][c4 * 4] = vv;
        }
        __syncthreads();

        for (int tt = 0; tt < TT; tt++) {
#if USE_TCGEN05
            const unsigned long long vd = dup2(vs[tt][j]);
            const ulonglong2 ea = *(const ulonglong2*)&es[tt][ig * 8];
            const ulonglong2 eb = *(const ulonglong2*)&es[tt][ig * 8 + 4];
            const ulonglong2 ka = *(const ulonglong2*)&ks[tt][ig * 8];
            const ulonglong2 kb2 = *(const ulonglong2*)&ks[tt][ig * 8 + 4];
            const ulonglong2 qa = *(const ulonglong2*)&qs[tt][ig * 8];
            const ulonglong2 qb2 = *(const ulonglong2*)&qs[tt][ig * 8 + 4];

            S01 = fma2(S01, ea.x, mul2(ka.x, vd));
            S23 = fma2(S23, ea.y, mul2(ka.y, vd));
            S45 = fma2(S45, eb.x, mul2(kb2.x, vd));
            S67 = fma2(S67, eb.y, mul2(kb2.y, vd));

            unsigned long long ap = mul2(qa.x, S01);
            ap = fma2(qa.y, S23, ap);
            ap = fma2(qb2.x, S45, ap);
            ap = fma2(qb2.y, S67, ap);
            float acc = hsum2(ap);
#else
            float vj  = vs[tt][j];
            float acc = 0.f;
#pragma unroll
            for (int r = 0; r < 8; r++) {
                int i = ig * 8 + r;
                float s = fmaf(S[r], es[tt][i], ks[tt][i] * vj);
                S[r] = s;
                acc = fmaf(qs[tt][i], s, acc);
            }
#endif
            acc += __shfl_xor_sync(0xffffffffu, acc, 4);
            acc += __shfl_xor_sync(0xffffffffu, acc, 2);
            acc += __shfl_xor_sync(0xffffffffu, acc, 1);
            if (ig == 0) ob[(size_t)(t0 + tt) * DMODEL + j] = acc;
        }
        __syncthreads();
    }
}

// ---------------------------------------------------------------------------
// LayerNorm(dv=128, no affine) + SiLU gate, fused hi/lo bf16 split of z
// ---------------------------------------------------------------------------
__global__ __launch_bounds__(256)
void ln_gate(const float* __restrict__ o, const float* __restrict__ gp,
             __nv_bfloat16* __restrict__ zh, __nv_bfloat16* __restrict__ zl)
{
    int gw   = (blockIdx.x * blockDim.x + threadIdx.x) >> 5;   // row id, 65536 total
    int lane = threadIdx.x & 31;

    float4 ov = ((const float4*)(o + (size_t)gw * 128))[lane];
    float s = ov.x + ov.y + ov.z + ov.w;
#pragma unroll
    for (int d = 16; d > 0; d >>= 1) s += __shfl_xor_sync(0xffffffffu, s, d);
    float mu = s * (1.f / 128.f);

    float dx0 = ov.x - mu, dx1 = ov.y - mu, dx2 = ov.z - mu, dx3 = ov.w - mu;
    float vsum = dx0 * dx0 + dx1 * dx1 + dx2 * dx2 + dx3 * dx3;
#pragma unroll
    for (int d = 16; d > 0; d >>= 1) vsum += __shfl_xor_sync(0xffffffffu, vsum, d);
    float inv = rsqrtf(vsum * (1.f / 128.f) + 1e-5f);

    float4 gv = ((const float4*)(gp + (size_t)gw * 128))[lane];
    float4 z;
    z.x = (gv.x / (1.f + __expf(-gv.x))) * (dx0 * inv);
    z.y = (gv.y / (1.f + __expf(-gv.y))) * (dx1 * inv);
    z.z = (gv.z / (1.f + __expf(-gv.z))) * (dx2 * inv);
    z.w = (gv.w / (1.f + __expf(-gv.w))) * (dx3 * inv);
    split4(z, zh, zl, gw * 32 + lane);
}

// ---------------------------------------------------------------------------
extern "C" void kernel_launch(void* const* d_in, const int* in_sizes, int n_in,
                              void* d_out, int out_size)
{
    const float* x    = (const float*)d_in[0];
    const float* Wq   = (const float*)d_in[1];
    const float* Wk   = (const float*)d_in[2];
    const float* Wkg1 = (const float*)d_in[3];
    const float* Wkg2 = (const float*)d_in[4];
    const float* bkg2 = (const float*)d_in[5];
    const float* Wv   = (const float*)d_in[6];
    const float* Wg   = (const float*)d_in[7];
    const float* bg   = (const float*)d_in[8];
    const float* Wo   = (const float*)d_in[9];
    float* out = (float*)d_out;

    float *q, *k, *kg, *v, *gp, *o;
    cudaGetSymbolAddress((void**)&q,   g_q);
    cudaGetSymbolAddress((void**)&k,   g_k);
    cudaGetSymbolAddress((void**)&kg,  g_kg);
    cudaGetSymbolAddress((void**)&v,   g_v);
    cudaGetSymbolAddress((void**)&gp,  g_gp);
    cudaGetSymbolAddress((void**)&o,   g_o);

    __nv_bfloat16 *xh, *xl, *zh, *zl;
    __nv_bfloat16 *wqh, *wql, *wkh, *wkl, *weh, *wel;
    __nv_bfloat16 *wvh, *wvl, *wgh, *wgl, *woh, *wol;
    cudaGetSymbolAddress((void**)&xh,  g_xh);  cudaGetSymbolAddress((void**)&xl,  g_xl);
    cudaGetSymbolAddress((void**)&zh,  g_zh);  cudaGetSymbolAddress((void**)&zl,  g_zl);
    cudaGetSymbolAddress((void**)&wqh, g_wqh); cudaGetSymbolAddress((void**)&wql, g_wql);
    cudaGetSymbolAddress((void**)&wkh, g_wkh); cudaGetSymbolAddress((void**)&wkl, g_wkl);
    cudaGetSymbolAddress((void**)&weh, g_weh); cudaGetSymbolAddress((void**)&wel, g_wel);
    cudaGetSymbolAddress((void**)&wvh, g_wvh); cudaGetSymbolAddress((void**)&wvl, g_wvl);
    cudaGetSymbolAddress((void**)&wgh, g_wgh); cudaGetSymbolAddress((void**)&wgl, g_wgl);
    cudaGetSymbolAddress((void**)&woh, g_woh); cudaGetSymbolAddress((void**)&wol, g_wol);

    cudaFuncSetAttribute(gemm3, cudaFuncAttributeMaxDynamicSharedMemorySize, GEMM_DSM);

    // splits + fused low-rank weight product
    split32<<<(MTOK * DMODEL) / 1024, 256>>>(x, xh, xl);
    split_w<<<16384, 256>>>(Wq, Wk, Wv, Wg, Wo,
                            wqh, wql, wkh, wkl, wvh, wvl, wgh, wgl, woh, wol);
    weff_split<<<dim3(16, 4), 256>>>(Wkg1, Wkg2, weh, wel);

    dim3 blk(GEMM_THREADS);
    dim3 gQK(DQK / 256, MTOK / 128);      // 4 x 32
    dim3 gD (DMODEL / 256, MTOK / 128);   // 8 x 32

    gemm3<<<gQK, blk, GEMM_DSM>>>(xh, xl, wqh, wql, nullptr, q,  DQK,    DMODEL, 1.f);
    gemm3<<<gQK, blk, GEMM_DSM>>>(xh, xl, wkh, wkl, nullptr, k,  DQK,    DMODEL, SCALE_K);
    gemm3<<<gQK, blk, GEMM_DSM>>>(xh, xl, weh, wel, bkg2,    kg, DQK,    DMODEL, 1.f);
    gemm3<<<gD,  blk, GEMM_DSM>>>(xh, xl, wvh, wvl, nullptr, v,  DMODEL, DMODEL, 1.f);
    gemm3<<<gD,  blk, GEMM_DSM>>>(xh, xl, wgh, wgl, bg,      gp, DMODEL, DMODEL, 1.f);

    gla_rec<<<256, 128>>>(q, k, kg, v, o);

    ln_gate<<<(MTOK * NHEAD * 32) / 256, 256>>>(o, gp, zh, zl);

    gemm3<<<gD, blk, GEMM_DSM>>>(zh, zl, woh, wol, nullptr, out, DMODEL, DMODEL, 1.f);
}

// round 10
// speedup vs baseline: 1.5006x; 1.5006x over previous
#include <cuda_runtime.h>
#include <cuda_bf16.h>
#include <math.h>
#include <cstdint>

// ---------------------------------------------------------------------------
// Problem constants: B=2, L=2048, D=2048, H=16, dk=64, dv=128.  M = B*L = 4096.
// ---------------------------------------------------------------------------
#define MTOK 4096
#define DMODEL 2048
#define DQK 1024
#define NHEAD 16
#define DK 64
#define DV 128
#define SEQ 2048
#define SCALE_K 0.08838834764831845f   // 128^-0.5
#define INV_NORM 0.0625f               // 1/16
#define CH 64                          // chunk length
#define NCK (SEQ / CH)                 // 32 chunks per (b,h)
#define BH (2 * NHEAD)                 // 32

// tcgen05 only exists in the arch-specific (sm_103a) compilation pass.
#if defined(__CUDA_ARCH__) && (__CUDA_ARCH__ == 1030) && defined(__CUDA_ARCH_FEAT_SM103_ALL)
#define USE_TCGEN05 1
#else
#define USE_TCGEN05 0
#endif

// ---------------------------------------------------------------------------
// Scratch (device globals: no allocation allowed)
// ---------------------------------------------------------------------------
__device__ float g_q [MTOK * DQK];
__device__ float g_k [MTOK * DQK];
__device__ float g_kg[MTOK * DQK];
__device__ float g_v [MTOK * DMODEL];
__device__ float g_gp[MTOK * DMODEL];
__device__ float g_o [MTOK * DMODEL];
__device__ float g_a [BH * SEQ * DK];             // prefix decay products
__device__ float g_U [BH * NCK * DK * DV];        // per-chunk K̂ᵀV
__device__ float g_Sp[BH * NCK * DK * DV];        // state BEFORE each chunk

__device__ __nv_bfloat16 g_xh[MTOK * DMODEL],   g_xl[MTOK * DMODEL];
__device__ __nv_bfloat16 g_zh[MTOK * DMODEL],   g_zl[MTOK * DMODEL];
__device__ __nv_bfloat16 g_wqh[DQK * DMODEL],   g_wql[DQK * DMODEL];
__device__ __nv_bfloat16 g_wkh[DQK * DMODEL],   g_wkl[DQK * DMODEL];
__device__ __nv_bfloat16 g_weh[DQK * DMODEL],   g_wel[DQK * DMODEL];   // Wkg2@Wkg1
__device__ __nv_bfloat16 g_wvh[DMODEL * DMODEL], g_wvl[DMODEL * DMODEL];
__device__ __nv_bfloat16 g_wgh[DMODEL * DMODEL], g_wgl[DMODEL * DMODEL];
__device__ __nv_bfloat16 g_woh[DMODEL * DMODEL], g_wol[DMODEL * DMODEL];

// ---------------------------------------------------------------------------
// PTX helpers
// ---------------------------------------------------------------------------
__device__ __forceinline__ uint32_t smem_u32(const void* p) {
    uint32_t a;
    asm("{ .reg .u64 t; cvta.to.shared.u64 t, %1; cvt.u32.u64 %0, t; }" : "=r"(a) : "l"(p));
    return a;
}

#define SWZ(o) ((o) ^ (((o) >> 3) & 0x70))

#define CP_ASYNC16(dst, src) \
    asm volatile("cp.async.cg.shared.global [%0], [%1], 16;" :: "r"(dst), "l"(src))
#define CP_ASYNC_MBAR_ARRIVE(mb) \
    asm volatile("cp.async.mbarrier.arrive.noinc.shared.b64 [%0];" :: "r"((uint32_t)(mb)) : "memory")
#define CP_ASYNC_COMMIT() \
    asm volatile("cp.async.commit_group;" ::: "memory")
#define CP_ASYNC_WAIT(n) \
    asm volatile("cp.async.wait_group %0;" :: "n"(n) : "memory")

#define MBARRIER_INIT(mb, cnt) \
    asm volatile("mbarrier.init.shared.b64 [%0], %1;" :: "r"((uint32_t)(mb)), "r"((uint32_t)(cnt)) : "memory")

#define MBARRIER_WAIT_PARITY(mb, par) do { \
    uint32_t _mb = (uint32_t)(mb); uint32_t _p = (uint32_t)(par); uint32_t _done; \
    asm volatile("{\n\t.reg .pred p;\n\t" \
        "mbarrier.try_wait.parity.acquire.cta.shared::cta.b64 p, [%1], %2;\n\t" \
        "selp.b32 %0, 1, 0, p;\n\t}" : "=r"(_done) : "r"(_mb), "r"(_p) : "memory"); \
    if (!_done) { \
        asm volatile("{\n\t.reg .pred P1;\n\t" \
            "WL_%=:\n\t" \
            "mbarrier.try_wait.parity.acquire.cta.shared::cta.b64 P1, [%0], %1, 0x989680;\n\t" \
            "@P1 bra.uni WD_%=;\n\t" \
            "bra.uni WL_%=;\n\t" \
            "WD_%=:\n\t}" :: "r"(_mb), "r"(_p) : "memory"); \
    } \
} while (0)

#if USE_TCGEN05
__device__ __forceinline__ uint32_t elect_one_pred() {
    uint32_t pred;
    asm volatile("{\n\t.reg .pred p;\n\telect.sync _|p, 0xFFFFFFFF;\n\t"
                 "selp.b32 %0, 1, 0, p;\n\t}" : "=r"(pred));
    return pred;
}

#define TCGEN05_ALLOC(smem_res, ncols) \
    asm volatile("tcgen05.alloc.cta_group::1.sync.aligned.shared::cta.b32 [%0], %1;" \
                 :: "r"((uint32_t)(smem_res)), "r"((uint32_t)(ncols)) : "memory")
#define TCGEN05_DEALLOC(tm, ncols) \
    asm volatile("tcgen05.dealloc.cta_group::1.sync.aligned.b32 %0, %1;" :: "r"(tm), "r"((uint32_t)(ncols)))
#define TCGEN05_RELINQ() \
    asm volatile("tcgen05.relinquish_alloc_permit.cta_group::1.sync.aligned;")
#define TCGEN05_COMMIT(mb) \
    asm volatile("tcgen05.commit.cta_group::1.mbarrier::arrive::one.shared::cluster.b64 [%0];" \
                 :: "r"((uint32_t)(mb)) : "memory")
#define TCGEN05_FENCE_AFTER() \
    asm volatile("tcgen05.fence::after_thread_sync;" ::: "memory")
#define TCGEN05_WAIT_LD() \
    asm volatile("tcgen05.wait::ld.sync.aligned;" ::: "memory")
#define FENCE_PROXY_ASYNC() \
    asm volatile("fence.proxy.async.shared::cta;" ::: "memory")

#define TCGEN05_LD_X32(r, tm) \
    asm volatile("tcgen05.ld.sync.aligned.32x32b.x32.b32 " \
        "{%0, %1, %2, %3, %4, %5, %6, %7, %8, %9, %10, %11, %12, %13, %14, %15, " \
        " %16, %17, %18, %19, %20, %21, %22, %23, %24, %25, %26, %27, %28, %29, %30, %31}, [%32];" \
        : "=r"((r)[0]),  "=r"((r)[1]),  "=r"((r)[2]),  "=r"((r)[3]), \
          "=r"((r)[4]),  "=r"((r)[5]),  "=r"((r)[6]),  "=r"((r)[7]), \
          "=r"((r)[8]),  "=r"((r)[9]),  "=r"((r)[10]), "=r"((r)[11]), \
          "=r"((r)[12]), "=r"((r)[13]), "=r"((r)[14]), "=r"((r)[15]), \
          "=r"((r)[16]), "=r"((r)[17]), "=r"((r)[18]), "=r"((r)[19]), \
          "=r"((r)[20]), "=r"((r)[21]), "=r"((r)[22]), "=r"((r)[23]), \
          "=r"((r)[24]), "=r"((r)[25]), "=r"((r)[26]), "=r"((r)[27]), \
          "=r"((r)[28]), "=r"((r)[29]), "=r"((r)[30]), "=r"((r)[31]) \
        : "r"(tm))

// K-major SW128 descriptor: layout=2 (SW128), version=1, SBO=64, LBO=1
static constexpr uint64_t DESC_BASE_SW128 =
    (uint64_t(2) << 61) | (uint64_t(1) << 46) | (uint64_t(64) << 32) | (uint64_t(1) << 16);
#define MAKE_DESC(addr) (DESC_BASE_SW128 | ((uint64_t)((addr) >> 4) & 0x3FFF))

__device__ __forceinline__ void mma_f16_ss(uint32_t d, uint64_t ad, uint64_t bd,
                                           uint32_t idesc, uint32_t en) {
    asm volatile("{\n\t.reg .pred p;\n\tsetp.ne.u32 p, %5, 0;\n\t"
        "tcgen05.mma.cta_group::1.kind::f16 [%0], %1, %2, %3, {%4, %4, %4, %4}, p;\n\t}"
        :: "r"(d), "l"(ad), "l"(bd), "r"(idesc), "r"(0u), "r"(en) : "memory");
}
#else
// HMMA fallback primitive: m16n8k16 row.col bf16 -> f32
__device__ __forceinline__ void mma16816(float* d, const uint32_t* a, const uint32_t* b) {
    asm volatile("mma.sync.aligned.m16n8k16.row.col.f32.bf16.bf16.f32 "
        "{%0,%1,%2,%3}, {%4,%5,%6,%7}, {%8,%9}, {%0,%1,%2,%3};"
        : "+f"(d[0]), "+f"(d[1]), "+f"(d[2]), "+f"(d[3])
        : "r"(a[0]), "r"(a[1]), "r"(a[2]), "r"(a[3]), "r"(b[0]), "r"(b[1]));
}
#endif

// ---------------------------------------------------------------------------
// bf16x3 GEMM:  C[M,N] = alpha * (A @ B^T) (+ bias), split hi/lo operands.
// Tile 128x256 (two N=128 MMA halves), K-chunk 64, WARP-SPECIALIZED.
// ---------------------------------------------------------------------------
#define BUFB 98304
#define GEMM_DSM (2 * BUFB + 1024)
#define GEMM_THREADS 288

__global__ __launch_bounds__(GEMM_THREADS) __cluster_dims__(1, 1, 1)
void gemm3(const __nv_bfloat16* __restrict__ Ah, const __nv_bfloat16* __restrict__ Al,
           const __nv_bfloat16* __restrict__ Bh, const __nv_bfloat16* __restrict__ Bl,
           const float* __restrict__ bias, float* __restrict__ C,
           int N, int K, float alpha)
{
    extern __shared__ char dsm[];

    const int tid = threadIdx.x;
    const int bm = blockIdx.y * 128;
    const int bn = blockIdx.x * 256;

    const uint32_t raw = smem_u32(dsm);
    const uint32_t sbase = (raw + 1023u) & ~1023u;
    char* sgen = dsm + (sbase - raw);

    const int NC = K / 64;

#if USE_TCGEN05
    __shared__ uint32_t s_tmem;
    __shared__ __align__(16) uint64_t s_full[2];
    __shared__ __align__(16) uint64_t s_empty[2];
    const uint32_t full0  = smem_u32(&s_full[0]),  full1  = smem_u32(&s_full[1]);
    const uint32_t empty0 = smem_u32(&s_empty[0]), empty1 = smem_u32(&s_empty[1]);

    if (tid < 32) { TCGEN05_ALLOC(smem_u32(&s_tmem), 256); TCGEN05_RELINQ(); }
    if (tid == 0) {
        MBARRIER_INIT(full0, 256);  MBARRIER_INIT(full1, 256);
        MBARRIER_INIT(empty0, 1);   MBARRIER_INIT(empty1, 1);
    }
    __syncthreads();
    const uint32_t tmem = s_tmem;

    if (tid < 256) {
        // ---------------- loader role ----------------
        const int lr  = tid >> 3;          // 0..31 base row
        const int seg = tid & 7;           // 16B segment within 128B row
        for (int c = 0; c < NC; c++) {
            if (c >= 2)
                MBARRIER_WAIT_PARITY((c & 1) ? empty1 : empty0, ((c - 2) >> 1) & 1);
            const uint32_t bb = sbase + (c & 1) * BUFB;
            const int k0 = c * 64;
#pragma unroll
            for (int t2 = 0; t2 < 2; t2++) {               // Ah, Al (128 rows)
                const __nv_bfloat16* basep = t2 ? Al : Ah;
                uint32_t tb = bb + t2 * 16384;
#pragma unroll
                for (int ii = 0; ii < 4; ii++) {
                    int r = lr + ii * 32;
                    const void* src = basep + (size_t)(bm + r) * K + k0 + seg * 8;
                    CP_ASYNC16(tb + SWZ((uint32_t)(r * 128 + seg * 16)), src);
                }
            }
#pragma unroll
            for (int t2 = 0; t2 < 2; t2++) {               // Bh, Bl (256 rows)
                const __nv_bfloat16* basep = t2 ? Bl : Bh;
                uint32_t tb = bb + 32768 + t2 * 32768;
#pragma unroll
                for (int ii = 0; ii < 8; ii++) {
                    int r = lr + ii * 32;
                    const void* src = basep + (size_t)(bn + r) * K + k0 + seg * 8;
                    CP_ASYNC16(tb + SWZ((uint32_t)(r * 128 + seg * 16)), src);
                }
            }
            CP_ASYNC_MBAR_ARRIVE((c & 1) ? full1 : full0);
        }
    } else if (elect_one_pred()) {
        // ---------------- MMA role (single elected thread of warp 8) --------
        const uint32_t IDESC = (1u << 4) | (1u << 7) | (1u << 10) | (16u << 17) | (8u << 24);
        for (int c = 0; c < NC; c++) {
            MBARRIER_WAIT_PARITY((c & 1) ? full1 : full0, (c >> 1) & 1);
            FENCE_PROXY_ASYNC();           // generic (cp.async) -> async proxy
            const uint32_t ab = sbase + (c & 1) * BUFB;
            const uint64_t dAh  = MAKE_DESC(ab);
            const uint64_t dAl  = MAKE_DESC(ab + 16384);
            const uint64_t dBh0 = MAKE_DESC(ab + 32768);
            const uint64_t dBh1 = MAKE_DESC(ab + 32768 + 16384);
            const uint64_t dBl0 = MAKE_DESC(ab + 65536);
            const uint64_t dBl1 = MAKE_DESC(ab + 65536 + 16384);
            const uint32_t en0 = (c > 0);
#pragma unroll
            for (int ks = 0; ks < 4; ks++)
                mma_f16_ss(tmem,       dAh + ks * 2, dBh0 + ks * 2, IDESC, en0 || (ks > 0));
#pragma unroll
            for (int ks = 0; ks < 4; ks++)
                mma_f16_ss(tmem + 128, dAh + ks * 2, dBh1 + ks * 2, IDESC, en0 || (ks > 0));
#pragma unroll
            for (int ks = 0; ks < 4; ks++) {
                mma_f16_ss(tmem,       dAh + ks * 2, dBl0 + ks * 2, IDESC, 1u);
                mma_f16_ss(tmem + 128, dAh + ks * 2, dBl1 + ks * 2, IDESC, 1u);
                mma_f16_ss(tmem,       dAl + ks * 2, dBh0 + ks * 2, IDESC, 1u);
                mma_f16_ss(tmem + 128, dAl + ks * 2, dBh1 + ks * 2, IDESC, 1u);
            }
            TCGEN05_COMMIT((c & 1) ? empty1 : empty0);
        }
    }

    __syncthreads();
    MBARRIER_WAIT_PARITY(((NC - 1) & 1) ? empty1 : empty0, ((NC - 1) >> 1) & 1);
    TCGEN05_FENCE_AFTER();
    __syncthreads();

    // epilogue: TMEM -> regs -> padded SMEM stage -> coalesced STG (8 slabs)
    float* stage = (float*)sgen;
    for (int slab = 0; slab < 8; slab++) {
        if (tid < 128) {
            uint32_t regs[32];
            TCGEN05_LD_X32(regs, tmem + slab * 32);
            TCGEN05_WAIT_LD();
#pragma unroll
            for (int cc = 0; cc < 32; cc++) stage[tid * 33 + cc] = __uint_as_float(regs[cc]);
        }
        __syncthreads();
        for (int e = tid; e < 4096; e += GEMM_THREADS) {
            int row = e >> 5, col = e & 31;
            float vv = stage[row * 33 + col] * alpha;
            if (bias) vv += bias[bn + slab * 32 + col];
            C[(size_t)(bm + row) * N + bn + slab * 32 + col] = vv;
        }
        __syncthreads();
    }
    if (tid < 32) TCGEN05_DEALLOC(tmem, 256);

#else  // ------------------- HMMA mma.sync fallback ------------------------
    const int warp = tid >> 5;
    const int lane = tid & 31;
    if (warp < 8) {
        const int wm = (warp & 3) * 32;
        const int wn = (warp >> 2) * 64;
        const int lg = lane >> 2;
        const int lt = lane & 3;
        const int lr  = tid >> 3;
        const int seg = tid & 7;

        auto load_chunk = [&](int c) {
            uint32_t bb = sbase + (c & 1) * BUFB;
            const int k0 = c * 64;
#pragma unroll
            for (int t2 = 0; t2 < 2; t2++) {
                const __nv_bfloat16* basep = t2 ? Al : Ah;
                uint32_t tb = bb + t2 * 16384;
#pragma unroll
                for (int ii = 0; ii < 4; ii++) {
                    int r = lr + ii * 32;
                    const void* src = basep + (size_t)(bm + r) * K + k0 + seg * 8;
                    CP_ASYNC16(tb + SWZ((uint32_t)(r * 128 + seg * 16)), src);
                }
            }
#pragma unroll
            for (int t2 = 0; t2 < 2; t2++) {
                const __nv_bfloat16* basep = t2 ? Bl : Bh;
                uint32_t tb = bb + 32768 + t2 * 32768;
#pragma unroll
                for (int ii = 0; ii < 8; ii++) {
                    int r = lr + ii * 32;
                    const void* src = basep + (size_t)(bn + r) * K + k0 + seg * 8;
                    CP_ASYNC16(tb + SWZ((uint32_t)(r * 128 + seg * 16)), src);
                }
            }
            CP_ASYNC_COMMIT();
        };

        for (int nh = 0; nh < 2; nh++) {
            float acc[2][8][4];
#pragma unroll
            for (int mt = 0; mt < 2; mt++)
#pragma unroll
                for (int nt = 0; nt < 8; nt++)
#pragma unroll
                    for (int r = 0; r < 4; r++) acc[mt][nt][r] = 0.f;

            load_chunk(0);
            for (int c = 0; c < NC; c++) {
                if (c + 1 < NC) { load_chunk(c + 1); CP_ASYNC_WAIT(1); }
                else            { CP_ASYNC_WAIT(0); }
                asm volatile("bar.sync 1, 256;" ::: "memory");

                char* bb = sgen + (c & 1) * BUFB;
                char* tAh = bb, *tAl = bb + 16384;
                char* tBh = bb + 32768 + nh * 16384, *tBl = bb + 65536 + nh * 16384;
#pragma unroll
                for (int kk = 0; kk < 64; kk += 16) {
                    const uint32_t kbase = (kk + lt * 2) * 2;
                    uint32_t bh[8][2], bl[8][2];
#pragma unroll
                    for (int nt = 0; nt < 8; nt++) {
                        uint32_t off = (uint32_t)((wn + nt * 8 + lg) * 128) + kbase;
                        bh[nt][0] = *(const uint32_t*)(tBh + SWZ(off));
                        bh[nt][1] = *(const uint32_t*)(tBh + SWZ(off + 16));
                        bl[nt][0] = *(const uint32_t*)(tBl + SWZ(off));
                        bl[nt][1] = *(const uint32_t*)(tBl + SWZ(off + 16));
                    }
#pragma unroll
                    for (int mt = 0; mt < 2; mt++) {
                        uint32_t o0 = (uint32_t)((wm + mt * 16 + lg) * 128) + kbase;
                        uint32_t o8 = o0 + 8 * 128;
                        uint32_t ah[4] = {
                            *(const uint32_t*)(tAh + SWZ(o0)),      *(const uint32_t*)(tAh + SWZ(o8)),
                            *(const uint32_t*)(tAh + SWZ(o0 + 16)), *(const uint32_t*)(tAh + SWZ(o8 + 16)) };
                        uint32_t al[4] = {
                            *(const uint32_t*)(tAl + SWZ(o0)),      *(const uint32_t*)(tAl + SWZ(o8)),
                            *(const uint32_t*)(tAl + SWZ(o0 + 16)), *(const uint32_t*)(tAl + SWZ(o8 + 16)) };
#pragma unroll
                        for (int nt = 0; nt < 8; nt++) mma16816(acc[mt][nt], ah, bh[nt]);
#pragma unroll
                        for (int nt = 0; nt < 8; nt++) mma16816(acc[mt][nt], ah, bl[nt]);
#pragma unroll
                        for (int nt = 0; nt < 8; nt++) mma16816(acc[mt][nt], al, bh[nt]);
                    }
                }
                asm volatile("bar.sync 1, 256;" ::: "memory");
            }
#pragma unroll
            for (int mt = 0; mt < 2; mt++) {
#pragma unroll
                for (int nt = 0; nt < 8; nt++) {
                    int row = bm + wm + mt * 16 + lg;
                    int col = bn + nh * 128 + wn + nt * 8 + lt * 2;
                    float b0 = bias ? bias[col]     : 0.f;
                    float b1 = bias ? bias[col + 1] : 0.f;
                    float2 v0 = { acc[mt][nt][0] * alpha + b0, acc[mt][nt][1] * alpha + b1 };
                    float2 v1 = { acc[mt][nt][2] * alpha + b0, acc[mt][nt][3] * alpha + b1 };
                    *(float2*)(C + (size_t)row * N + col)       = v0;
                    *(float2*)(C + (size_t)(row + 8) * N + col) = v1;
                }
            }
            asm volatile("bar.sync 1, 256;" ::: "memory");
        }
    }
#endif
}

// ---------------------------------------------------------------------------
// fp32 -> (hi, lo) bf16 split, vectorized by 4
// ---------------------------------------------------------------------------
__device__ __forceinline__ void split4(const float4 v,
                                       __nv_bfloat16* hi, __nv_bfloat16* lo, int i)
{
    __nv_bfloat16 h0 = __float2bfloat16(v.x), h1 = __float2bfloat16(v.y);
    __nv_bfloat16 h2 = __float2bfloat16(v.z), h3 = __float2bfloat16(v.w);
    __nv_bfloat16 l0 = __float2bfloat16(v.x - __bfloat162float(h0));
    __nv_bfloat16 l1 = __float2bfloat16(v.y - __bfloat162float(h1));
    __nv_bfloat16 l2 = __float2bfloat16(v.z - __bfloat162float(h2));
    __nv_bfloat16 l3 = __float2bfloat16(v.w - __bfloat162float(h3));
    ushort4 ph = { __bfloat16_as_ushort(h0), __bfloat16_as_ushort(h1),
                   __bfloat16_as_ushort(h2), __bfloat16_as_ushort(h3) };
    ushort4 pl = { __bfloat16_as_ushort(l0), __bfloat16_as_ushort(l1),
                   __bfloat16_as_ushort(l2), __bfloat16_as_ushort(l3) };
    ((ushort4*)hi)[i] = ph;
    ((ushort4*)lo)[i] = pl;
}

__global__ __launch_bounds__(256)
void split32(const float* __restrict__ s, __nv_bfloat16* __restrict__ hi,
             __nv_bfloat16* __restrict__ lo)
{
    int i = blockIdx.x * blockDim.x + threadIdx.x;
    split4(((const float4*)s)[i], hi, lo, i);
}

// One launch splitting all five weight matrices.
__global__ __launch_bounds__(256)
void split_w(const float* __restrict__ Wq, const float* __restrict__ Wk,
             const float* __restrict__ Wv, const float* __restrict__ Wg,
             const float* __restrict__ Wo,
             __nv_bfloat16* __restrict__ wqh, __nv_bfloat16* __restrict__ wql,
             __nv_bfloat16* __restrict__ wkh, __nv_bfloat16* __restrict__ wkl,
             __nv_bfloat16* __restrict__ wvh, __nv_bfloat16* __restrict__ wvl,
             __nv_bfloat16* __restrict__ wgh, __nv_bfloat16* __restrict__ wgl,
             __nv_bfloat16* __restrict__ woh, __nv_bfloat16* __restrict__ wol)
{
    int b = blockIdx.x;
    const float* src; __nv_bfloat16 *hi, *lo;
    if      (b < 2048)  { src = Wq; hi = wqh; lo = wql; }
    else if (b < 4096)  { src = Wk; hi = wkh; lo = wkl; b -= 2048; }
    else if (b < 8192)  { src = Wv; hi = wvh; lo = wvl; b -= 4096; }
    else if (b < 12288) { src = Wg; hi = wgh; lo = wgl; b -= 8192; }
    else                { src = Wo; hi = woh; lo = wol; b -= 12288; }
    int i = b * 256 + threadIdx.x;
    split4(((const float4*)src)[i], hi, lo, i);
}

// ---------------------------------------------------------------------------
// W_eff = Wkg2 @ Wkg1  ([1024,16] @ [16,2048] -> [1024,2048]), fused hi/lo split.
// ---------------------------------------------------------------------------
__global__ __launch_bounds__(256)
void weff_split(const float* __restrict__ W1,   // Wkg1 [16, 2048]
                const float* __restrict__ W2,   // Wkg2 [1024, 16]
                __nv_bfloat16* __restrict__ weh, __nv_bfloat16* __restrict__ wel)
{
    __shared__ __align__(16) float s1[16][128];
    const int tid = threadIdx.x;
    const int d0  = blockIdx.x * 128;
    const int n0  = blockIdx.y * 256;

#pragma unroll
    for (int it = 0; it < 2; it++) {
        int i = it * 256 + tid;
        int r = i >> 5, c4 = i & 31;
        *(float4*)&s1[r][c4 * 4] = *(const float4*)(W1 + r * DMODEL + d0 + c4 * 4);
    }
    __syncthreads();

    const int d4 = tid & 31;
    const int nb = tid >> 5;
    for (int n = n0 + nb; n < n0 + 256; n += 8) {
        const float4 w2a = *(const float4*)(W2 + n * 16);
        const float4 w2b = *(const float4*)(W2 + n * 16 + 4);
        const float4 w2c = *(const float4*)(W2 + n * 16 + 8);
        const float4 w2d = *(const float4*)(W2 + n * 16 + 12);
        float w2[16] = { w2a.x, w2a.y, w2a.z, w2a.w, w2b.x, w2b.y, w2b.z, w2b.w,
                         w2c.x, w2c.y, w2c.z, w2c.w, w2d.x, w2d.y, w2d.z, w2d.w };
        float4 acc = {0.f, 0.f, 0.f, 0.f};
#pragma unroll
        for (int r = 0; r < 16; r++) {
            float4 v = *(const float4*)&s1[r][d4 * 4];
            acc.x = fmaf(w2[r], v.x, acc.x);
            acc.y = fmaf(w2[r], v.y, acc.y);
            acc.z = fmaf(w2[r], v.z, acc.z);
            acc.w = fmaf(w2[r], v.w, acc.w);
        }
        split4(acc, weh, wel, n * (DMODEL / 4) + (d0 >> 2) + d4);
    }
}

// ===========================================================================
// CHUNKED GLA SCAN (exact algebra; fp32).  Chunk length CH=64.
//   a_t   = prod_{u<=t} lambda_u   (per dk element, within chunk)
//   U     = sum_s diag(a64/a_s) k_s v_s^T          (phase A)
//   S_c   = diag(a64) S_{c-1} + U_c  (sequential)  (phase B; stores S BEFORE)
//   o_t   = (q_t*a_t) S_pre + tril(Qt Kt^T) V      (phase C)
//           with Qt = q*a_t, Kt = k/a_s
// ===========================================================================

// ---------- Phase A: per-chunk U and decay table -----------------------------
// grid 1024 (= bh*32 + c), 256 threads.  dyn smem: lam 16K | kh 16K | v 32K.
#define PHA_SMEM (16384 * 4)
__global__ __launch_bounds__(256)
void gla_pha(const float* __restrict__ k, const float* __restrict__ kg,
             const float* __restrict__ v, float* __restrict__ a_g,
             float* __restrict__ U_g)
{
    extern __shared__ float sa[];
    float* lam = sa;                 // [64][64]
    float* kh  = sa + 4096;          // [64][64]
    float* vsm = sa + 8192;          // [64][128]

    const int blk = blockIdx.x;
    const int c   = blk & (NCK - 1);
    const int bh  = blk >> 5;
    const int b   = bh >> 4, h = bh & 15;
    const int t0  = c * CH;
    const int tid = threadIdx.x;

    const float* kb = k  + (size_t)b * SEQ * DQK    + h * DK;
    const float* gb = kg + (size_t)b * SEQ * DQK    + h * DK;
    const float* vb = v  + (size_t)b * SEQ * DMODEL + h * DV;
    float* ag = a_g + ((size_t)bh * SEQ + t0) * DK;
    float* Ug = U_g + (size_t)blk * (DK * DV);

    // lambda
    for (int e = tid; e < CH * DK; e += 256) {
        int t = e >> 6, i = e & 63;
        float x = gb[(size_t)(t0 + t) * DQK + i];
        float ls = fminf(x, 0.f) - log1pf(__expf(-fabsf(x)));
        lam[t * DK + i] = __expf(ls * INV_NORM);
    }
    // stage v
    for (int e = tid; e < CH * (DV / 4); e += 256) {
        int t = e >> 5, j4 = e & 31;
        *(float4*)&vsm[t * DV + j4 * 4] =
            *(const float4*)&vb[(size_t)(t0 + t) * DMODEL + j4 * 4];
    }
    __syncthreads();

    // prefix a (write to global) + suffix-weighted khat
    if (tid < DK) {
        const int i = tid;
        float acc = 1.f;
        for (int t = 0; t < CH; t++) {
            acc *= lam[t * DK + i];
            ag[(size_t)t * DK + i] = acc;
        }
        float w = 1.f;
        for (int t = CH - 1; t >= 0; t--) {
            kh[t * DK + i] = kb[(size_t)(t0 + t) * DQK + i] * w;
            w *= lam[t * DK + i];
        }
    }
    __syncthreads();

    // U[i][j] = sum_s kh[s][i] * v[s][j] ; thread owns 8 i x 4 j
    {
        const int i0 = (tid >> 5) * 8;
        const int j0 = (tid & 31) * 4;
        float acc[8][4];
#pragma unroll
        for (int ii = 0; ii < 8; ii++)
#pragma unroll
            for (int jj = 0; jj < 4; jj++) acc[ii][jj] = 0.f;

        for (int s = 0; s < CH; s++) {
            float4 va = *(const float4*)&vsm[s * DV + j0];
            float kv[8];
            *(float4*)&kv[0] = *(const float4*)&kh[s * DK + i0];
            *(float4*)&kv[4] = *(const float4*)&kh[s * DK + i0 + 4];
#pragma unroll
            for (int ii = 0; ii < 8; ii++) {
                acc[ii][0] = fmaf(kv[ii], va.x, acc[ii][0]);
                acc[ii][1] = fmaf(kv[ii], va.y, acc[ii][1]);
                acc[ii][2] = fmaf(kv[ii], va.z, acc[ii][2]);
                acc[ii][3] = fmaf(kv[ii], va.w, acc[ii][3]);
            }
        }
#pragma unroll
        for (int ii = 0; ii < 8; ii++) {
            float4 w4 = { acc[ii][0], acc[ii][1], acc[ii][2], acc[ii][3] };
            *(float4*)&Ug[(size_t)(i0 + ii) * DV + j0] = w4;
        }
    }
}

// ---------- Phase B: sequential state scan (32 blocks, regs) ----------------
__global__ __launch_bounds__(256)
void gla_phb(const float* __restrict__ a_g, const float* __restrict__ U_g,
             float* __restrict__ Sp_g)
{
    const int bh  = blockIdx.x;
    const int tid = threadIdx.x;
    float S[32];
#pragma unroll
    for (int w = 0; w < 32; w++) S[w] = 0.f;

    for (int c = 0; c < NCK; c++) {
        const float* Ug = U_g + ((size_t)bh * NCK + c) * (DK * DV);
        float* Sg = Sp_g + ((size_t)bh * NCK + c) * (DK * DV);
        const float* a64 = a_g + ((size_t)bh * SEQ + c * CH + CH - 1) * DK;
#pragma unroll
        for (int w = 0; w < 8; w++) {
            int f4 = tid + w * 256;            // 0..2047
            int i = f4 >> 5;
            float ai = a64[i];
            float4 u = ((const float4*)Ug)[f4];
            float4 s = *(float4*)&S[w * 4];
            ((float4*)Sg)[f4] = s;             // state BEFORE chunk c
            s.x = fmaf(s.x, ai, u.x);
            s.y = fmaf(s.y, ai, u.y);
            s.z = fmaf(s.z, ai, u.z);
            s.w = fmaf(s.w, ai, u.w);
            *(float4*)&S[w * 4] = s;
        }
    }
}

// ---------- Phase C: per-chunk output ---------------------------------------
// grid 1024, 256 threads.
// dyn smem floats: qt [64][68] @0 | kT [64][68] @4352 | A [64][65] @8704 |
//                  v  [64][128] @12864 | Sp [64][128] @21056   (29248 floats)
#define PHC_SMEM (29248 * 4)
__global__ __launch_bounds__(256)
void gla_phc(const float* __restrict__ q, const float* __restrict__ a_g,
             const float* __restrict__ k, const float* __restrict__ Sp_g,
             const float* __restrict__ v, float* __restrict__ o)
{
    extern __shared__ float sc[];
    float* qt  = sc;            // [64][68]  row stride 68
    float* kT  = sc + 4352;     // [64(i)][68(s)]
    float* Am  = sc + 8704;     // [64][65]
    float* vsm = sc + 12864;    // [64][128]
    float* Ssm = sc + 21056;    // [64][128]

    const int blk = blockIdx.x;
    const int c   = blk & (NCK - 1);
    const int bh  = blk >> 5;
    const int b   = bh >> 4, h = bh & 15;
    const int t0  = c * CH;
    const int tid = threadIdx.x;

    const float* qb = q + (size_t)b * SEQ * DQK + h * DK;
    const float* kb = k + (size_t)b * SEQ * DQK + h * DK;
    const float* vb = v + (size_t)b * SEQ * DMODEL + h * DV;
    const float* ag = a_g + ((size_t)bh * SEQ + t0) * DK;
    const float* Sg = Sp_g + (size_t)blk * (DK * DV);
    float* ob = o + (size_t)b * SEQ * DMODEL + h * DV;

    // build qt (q*a) and kT (k/a, transposed i-major)
    for (int e = tid; e < CH * DK; e += 256) {
        int t = e >> 6, i = e & 63;
        float aa = ag[(size_t)t * DK + i];
        qt[t * 68 + i] = qb[(size_t)(t0 + t) * DQK + i] * aa;
        kT[i * 68 + t] = kb[(size_t)(t0 + t) * DQK + i] / aa;
    }
    // stage v and S_pre
    for (int e = tid; e < CH * (DV / 4); e += 256) {
        int t = e >> 5, j4 = e & 31;
        *(float4*)&vsm[t * DV + j4 * 4] =
            *(const float4*)&vb[(size_t)(t0 + t) * DMODEL + j4 * 4];
        *(float4*)&Ssm[t * DV + j4 * 4] = ((const float4*)Sg)[e];
    }
    __syncthreads();

    // A = tril(qt @ kT)  ; thread owns (t, 16 s)
    {
        const int t  = tid >> 2;
        const int s0 = (tid & 3) * 16;
        float acc[16];
#pragma unroll
        for (int ss = 0; ss < 16; ss++) acc[ss] = 0.f;
        for (int i = 0; i < DK; i++) {
            float qv = qt[t * 68 + i];
            const float* kr = &kT[i * 68 + s0];
            float4 k0 = *(const float4*)&kr[0];
            float4 k1 = *(const float4*)&kr[4];
            float4 k2 = *(const float4*)&kr[8];
            float4 k3 = *(const float4*)&kr[12];
            acc[0]  = fmaf(qv, k0.x, acc[0]);  acc[1]  = fmaf(qv, k0.y, acc[1]);
            acc[2]  = fmaf(qv, k0.z, acc[2]);  acc[3]  = fmaf(qv, k0.w, acc[3]);
            acc[4]  = fmaf(qv, k1.x, acc[4]);  acc[5]  = fmaf(qv, k1.y, acc[5]);
            acc[6]  = fmaf(qv, k1.z, acc[6]);  acc[7]  = fmaf(qv, k1.w, acc[7]);
            acc[8]  = fmaf(qv, k2.x, acc[8]);  acc[9]  = fmaf(qv, k2.y, acc[9]);
            acc[10] = fmaf(qv, k2.z, acc[10]); acc[11] = fmaf(qv, k2.w, acc[11]);
            acc[12] = fmaf(qv, k3.x, acc[12]); acc[13] = fmaf(qv, k3.y, acc[13]);
            acc[14] = fmaf(qv, k3.z, acc[14]); acc[15] = fmaf(qv, k3.w, acc[15]);
        }
#pragma unroll
        for (int ss = 0; ss < 16; ss++) {
            int s = s0 + ss;
            Am[t * 65 + s] = (s <= t) ? acc[ss] : 0.f;
        }
    }
    __syncthreads();

    // o = A @ V (tril: s<=t) + qt @ S_pre ; thread owns (t, 32 j)
    {
        const int t  = tid >> 2;
        const int j0 = (tid & 3) * 32;
        float acc[32];
#pragma unroll
        for (int jj = 0; jj < 32; jj++) acc[jj] = 0.f;

        for (int s = 0; s <= t; s++) {
            float As = Am[t * 65 + s];
            const float* vr = &vsm[s * DV + j0];
#pragma unroll
            for (int q8 = 0; q8 < 8; q8++) {
                float4 vv = *(const float4*)&vr[q8 * 4];
                acc[q8 * 4 + 0] = fmaf(As, vv.x, acc[q8 * 4 + 0]);
                acc[q8 * 4 + 1] = fmaf(As, vv.y, acc[q8 * 4 + 1]);
                acc[q8 * 4 + 2] = fmaf(As, vv.z, acc[q8 * 4 + 2]);
                acc[q8 * 4 + 3] = fmaf(As, vv.w, acc[q8 * 4 + 3]);
            }
        }
        for (int i = 0; i < DK; i++) {
            float qv = qt[t * 68 + i];
            const float* sr = &Ssm[i * DV + j0];
#pragma unroll
            for (int q8 = 0; q8 < 8; q8++) {
                float4 sv = *(const float4*)&sr[q8 * 4];
                acc[q8 * 4 + 0] = fmaf(qv, sv.x, acc[q8 * 4 + 0]);
                acc[q8 * 4 + 1] = fmaf(qv, sv.y, acc[q8 * 4 + 1]);
                acc[q8 * 4 + 2] = fmaf(qv, sv.z, acc[q8 * 4 + 2]);
                acc[q8 * 4 + 3] = fmaf(qv, sv.w, acc[q8 * 4 + 3]);
            }
        }
        float* orow = ob + (size_t)(t0 + t) * DMODEL + j0;
#pragma unroll
        for (int q8 = 0; q8 < 8; q8++) {
            float4 w4 = { acc[q8 * 4 + 0], acc[q8 * 4 + 1],
                          acc[q8 * 4 + 2], acc[q8 * 4 + 3] };
            *(float4*)&orow[q8 * 4] = w4;
        }
    }
}

// ---------------------------------------------------------------------------
// LayerNorm(dv=128, no affine) + SiLU gate, fused hi/lo bf16 split of z
// ---------------------------------------------------------------------------
__global__ __launch_bounds__(256)
void ln_gate(const float* __restrict__ o, const float* __restrict__ gp,
             __nv_bfloat16* __restrict__ zh, __nv_bfloat16* __restrict__ zl)
{
    int gw   = (blockIdx.x * blockDim.x + threadIdx.x) >> 5;   // row id, 65536 total
    int lane = threadIdx.x & 31;

    float4 ov = ((const float4*)(o + (size_t)gw * 128))[lane];
    float s = ov.x + ov.y + ov.z + ov.w;
#pragma unroll
    for (int d = 16; d > 0; d >>= 1) s += __shfl_xor_sync(0xffffffffu, s, d);
    float mu = s * (1.f / 128.f);

    float dx0 = ov.x - mu, dx1 = ov.y - mu, dx2 = ov.z - mu, dx3 = ov.w - mu;
    float vsum = dx0 * dx0 + dx1 * dx1 + dx2 * dx2 + dx3 * dx3;
#pragma unroll
    for (int d = 16; d > 0; d >>= 1) vsum += __shfl_xor_sync(0xffffffffu, vsum, d);
    float inv = rsqrtf(vsum * (1.f / 128.f) + 1e-5f);

    float4 gv = ((const float4*)(gp + (size_t)gw * 128))[lane];
    float4 z;
    z.x = (gv.x / (1.f + __expf(-gv.x))) * (dx0 * inv);
    z.y = (gv.y / (1.f + __expf(-gv.y))) * (dx1 * inv);
    z.z = (gv.z / (1.f + __expf(-gv.z))) * (dx2 * inv);
    z.w = (gv.w / (1.f + __expf(-gv.w))) * (dx3 * inv);
    split4(z, zh, zl, gw * 32 + lane);
}

// ---------------------------------------------------------------------------
extern "C" void kernel_launch(void* const* d_in, const int* in_sizes, int n_in,
                              void* d_out, int out_size)
{
    const float* x    = (const float*)d_in[0];
    const float* Wq   = (const float*)d_in[1];
    const float* Wk   = (const float*)d_in[2];
    const float* Wkg1 = (const float*)d_in[3];
    const float* Wkg2 = (const float*)d_in[4];
    const float* bkg2 = (const float*)d_in[5];
    const float* Wv   = (const float*)d_in[6];
    const float* Wg   = (const float*)d_in[7];
    const float* bg   = (const float*)d_in[8];
    const float* Wo   = (const float*)d_in[9];
    float* out = (float*)d_out;

    float *q, *k, *kg, *v, *gp, *o, *ad, *Ud, *Sp;
    cudaGetSymbolAddress((void**)&q,   g_q);
    cudaGetSymbolAddress((void**)&k,   g_k);
    cudaGetSymbolAddress((void**)&kg,  g_kg);
    cudaGetSymbolAddress((void**)&v,   g_v);
    cudaGetSymbolAddress((void**)&gp,  g_gp);
    cudaGetSymbolAddress((void**)&o,   g_o);
    cudaGetSymbolAddress((void**)&ad,  g_a);
    cudaGetSymbolAddress((void**)&Ud,  g_U);
    cudaGetSymbolAddress((void**)&Sp,  g_Sp);

    __nv_bfloat16 *xh, *xl, *zh, *zl;
    __nv_bfloat16 *wqh, *wql, *wkh, *wkl, *weh, *wel;
    __nv_bfloat16 *wvh, *wvl, *wgh, *wgl, *woh, *wol;
    cudaGetSymbolAddress((void**)&xh,  g_xh);  cudaGetSymbolAddress((void**)&xl,  g_xl);
    cudaGetSymbolAddress((void**)&zh,  g_zh);  cudaGetSymbolAddress((void**)&zl,  g_zl);
    cudaGetSymbolAddress((void**)&wqh, g_wqh); cudaGetSymbolAddress((void**)&wql, g_wql);
    cudaGetSymbolAddress((void**)&wkh, g_wkh); cudaGetSymbolAddress((void**)&wkl, g_wkl);
    cudaGetSymbolAddress((void**)&weh, g_weh); cudaGetSymbolAddress((void**)&wel, g_wel);
    cudaGetSymbolAddress((void**)&wvh, g_wvh); cudaGetSymbolAddress((void**)&wvl, g_wvl);
    cudaGetSymbolAddress((void**)&wgh, g_wgh); cudaGetSymbolAddress((void**)&wgl, g_wgl);
    cudaGetSymbolAddress((void**)&woh, g_woh); cudaGetSymbolAddress((void**)&wol, g_wol);

    cudaFuncSetAttribute(gemm3, cudaFuncAttributeMaxDynamicSharedMemorySize, GEMM_DSM);
    cudaFuncSetAttribute(gla_pha, cudaFuncAttributeMaxDynamicSharedMemorySize, PHA_SMEM);
    cudaFuncSetAttribute(gla_phc, cudaFuncAttributeMaxDynamicSharedMemorySize, PHC_SMEM);

    // splits + fused low-rank weight product
    split32<<<(MTOK * DMODEL) / 1024, 256>>>(x, xh, xl);
    split_w<<<16384, 256>>>(Wq, Wk, Wv, Wg, Wo,
                            wqh, wql, wkh, wkl, wvh, wvl, wgh, wgl, woh, wol);
    weff_split<<<dim3(16, 4), 256>>>(Wkg1, Wkg2, weh, wel);

    dim3 blk(GEMM_THREADS);
    dim3 gQK(DQK / 256, MTOK / 128);      // 4 x 32
    dim3 gD (DMODEL / 256, MTOK / 128);   // 8 x 32

    gemm3<<<gQK, blk, GEMM_DSM>>>(xh, xl, wqh, wql, nullptr, q,  DQK,    DMODEL, 1.f);
    gemm3<<<gQK, blk, GEMM_DSM>>>(xh, xl, wkh, wkl, nullptr, k,  DQK,    DMODEL, SCALE_K);
    gemm3<<<gQK, blk, GEMM_DSM>>>(xh, xl, weh, wel, bkg2,    kg, DQK,    DMODEL, 1.f);
    gemm3<<<gD,  blk, GEMM_DSM>>>(xh, xl, wvh, wvl, nullptr, v,  DMODEL, DMODEL, 1.f);
    gemm3<<<gD,  blk, GEMM_DSM>>>(xh, xl, wgh, wgl, bg,      gp, DMODEL, DMODEL, 1.f);

    // chunked scan
    gla_pha<<<BH * NCK, 256, PHA_SMEM>>>(k, kg, v, ad, Ud);
    gla_phb<<<BH, 256>>>(ad, Ud, Sp);
    gla_phc<<<BH * NCK, 256, PHC_SMEM>>>(q, ad, k, Sp, v, o);

    ln_gate<<<(MTOK * NHEAD * 32) / 256, 256>>>(o, gp, zh, zl);

    gemm3<<<gD, blk, GEMM_DSM>>>(zh, zl, woh, wol, nullptr, out, DMODEL, DMODEL, 1.f);
}

// round 11
// speedup vs baseline: 2.1873x; 1.4577x over previous
#include <cuda_runtime.h>
#include <cuda_bf16.h>
#include <math.h>
#include <cstdint>

// ---------------------------------------------------------------------------
// Problem constants: B=2, L=2048, D=2048, H=16, dk=64, dv=128.  M = B*L = 4096.
// ---------------------------------------------------------------------------
#define MTOK 4096
#define DMODEL 2048
#define DQK 1024
#define NHEAD 16
#define DK 64
#define DV 128
#define SEQ 2048
#define SCALE_K 0.08838834764831845f   // 128^-0.5
#define INV_NORM 0.0625f               // 1/16
#define CH 64                          // chunk length
#define NCK (SEQ / CH)                 // 32 chunks per (b,h)
#define BH (2 * NHEAD)                 // 32
#define QS 3072                        // row stride of fused [q|k|kg]
#define VS 4096                        // row stride of fused [v|gp]

#if defined(__CUDA_ARCH__) && (__CUDA_ARCH__ == 1030) && defined(__CUDA_ARCH_FEAT_SM103_ALL)
#define USE_TCGEN05 1
#else
#define USE_TCGEN05 0
#endif

// ---------------------------------------------------------------------------
// Scratch (device globals: no allocation allowed)
// ---------------------------------------------------------------------------
__device__ float g_qkg[MTOK * QS];                // [q | k*scale | kg]
__device__ float g_vg [MTOK * VS];                // [v | gp]
__device__ float g_o  [MTOK * DMODEL];
__device__ float g_a  [BH * SEQ * DK];            // prefix decay products
__device__ float g_U  [BH * NCK * DK * DV];       // per-chunk K̂ᵀV
__device__ float g_Sp [BH * NCK * DK * DV];       // state BEFORE each chunk
__device__ float g_bqkg[QS], g_bvg[VS];           // fused bias vectors

__device__ __nv_bfloat16 g_xh[MTOK * DMODEL],  g_xl[MTOK * DMODEL];
__device__ __nv_bfloat16 g_zh[MTOK * DMODEL],  g_zl[MTOK * DMODEL];
__device__ __nv_bfloat16 g_wqkh[QS * DMODEL],  g_wqkl[QS * DMODEL];
__device__ __nv_bfloat16 g_wvgh[VS * DMODEL],  g_wvgl[VS * DMODEL];
__device__ __nv_bfloat16 g_woh[DMODEL * DMODEL], g_wol[DMODEL * DMODEL];

// ---------------------------------------------------------------------------
// PTX helpers
// ---------------------------------------------------------------------------
__device__ __forceinline__ uint32_t smem_u32(const void* p) {
    uint32_t a;
    asm("{ .reg .u64 t; cvta.to.shared.u64 t, %1; cvt.u32.u64 %0, t; }" : "=r"(a) : "l"(p));
    return a;
}

#define SWZ(o) ((o) ^ (((o) >> 3) & 0x70))

#define CP_ASYNC16(dst, src) \
    asm volatile("cp.async.cg.shared.global [%0], [%1], 16;" :: "r"(dst), "l"(src))
#define CP_ASYNC_MBAR_ARRIVE(mb) \
    asm volatile("cp.async.mbarrier.arrive.noinc.shared.b64 [%0];" :: "r"((uint32_t)(mb)) : "memory")
#define CP_ASYNC_COMMIT() \
    asm volatile("cp.async.commit_group;" ::: "memory")
#define CP_ASYNC_WAIT(n) \
    asm volatile("cp.async.wait_group %0;" :: "n"(n) : "memory")

#define MBARRIER_INIT(mb, cnt) \
    asm volatile("mbarrier.init.shared.b64 [%0], %1;" :: "r"((uint32_t)(mb)), "r"((uint32_t)(cnt)) : "memory")

#define MBARRIER_WAIT_PARITY(mb, par) do { \
    uint32_t _mb = (uint32_t)(mb); uint32_t _p = (uint32_t)(par); uint32_t _done; \
    asm volatile("{\n\t.reg .pred p;\n\t" \
        "mbarrier.try_wait.parity.acquire.cta.shared::cta.b64 p, [%1], %2;\n\t" \
        "selp.b32 %0, 1, 0, p;\n\t}" : "=r"(_done) : "r"(_mb), "r"(_p) : "memory"); \
    if (!_done) { \
        asm volatile("{\n\t.reg .pred P1;\n\t" \
            "WL_%=:\n\t" \
            "mbarrier.try_wait.parity.acquire.cta.shared::cta.b64 P1, [%0], %1, 0x989680;\n\t" \
            "@P1 bra.uni WD_%=;\n\t" \
            "bra.uni WL_%=;\n\t" \
            "WD_%=:\n\t}" :: "r"(_mb), "r"(_p) : "memory"); \
    } \
} while (0)

#if USE_TCGEN05
__device__ __forceinline__ uint32_t elect_one_pred() {
    uint32_t pred;
    asm volatile("{\n\t.reg .pred p;\n\telect.sync _|p, 0xFFFFFFFF;\n\t"
                 "selp.b32 %0, 1, 0, p;\n\t}" : "=r"(pred));
    return pred;
}

#define TCGEN05_ALLOC(smem_res, ncols) \
    asm volatile("tcgen05.alloc.cta_group::1.sync.aligned.shared::cta.b32 [%0], %1;" \
                 :: "r"((uint32_t)(smem_res)), "r"((uint32_t)(ncols)) : "memory")
#define TCGEN05_DEALLOC(tm, ncols) \
    asm volatile("tcgen05.dealloc.cta_group::1.sync.aligned.b32 %0, %1;" :: "r"(tm), "r"((uint32_t)(ncols)))
#define TCGEN05_RELINQ() \
    asm volatile("tcgen05.relinquish_alloc_permit.cta_group::1.sync.aligned;")
#define TCGEN05_COMMIT(mb) \
    asm volatile("tcgen05.commit.cta_group::1.mbarrier::arrive::one.shared::cluster.b64 [%0];" \
                 :: "r"((uint32_t)(mb)) : "memory")
#define TCGEN05_FENCE_AFTER() \
    asm volatile("tcgen05.fence::after_thread_sync;" ::: "memory")
#define TCGEN05_WAIT_LD() \
    asm volatile("tcgen05.wait::ld.sync.aligned;" ::: "memory")
#define FENCE_PROXY_ASYNC() \
    asm volatile("fence.proxy.async.shared::cta;" ::: "memory")

#define TCGEN05_LD_X32(r, tm) \
    asm volatile("tcgen05.ld.sync.aligned.32x32b.x32.b32 " \
        "{%0, %1, %2, %3, %4, %5, %6, %7, %8, %9, %10, %11, %12, %13, %14, %15, " \
        " %16, %17, %18, %19, %20, %21, %22, %23, %24, %25, %26, %27, %28, %29, %30, %31}, [%32];" \
        : "=r"((r)[0]),  "=r"((r)[1]),  "=r"((r)[2]),  "=r"((r)[3]), \
          "=r"((r)[4]),  "=r"((r)[5]),  "=r"((r)[6]),  "=r"((r)[7]), \
          "=r"((r)[8]),  "=r"((r)[9]),  "=r"((r)[10]), "=r"((r)[11]), \
          "=r"((r)[12]), "=r"((r)[13]), "=r"((r)[14]), "=r"((r)[15]), \
          "=r"((r)[16]), "=r"((r)[17]), "=r"((r)[18]), "=r"((r)[19]), \
          "=r"((r)[20]), "=r"((r)[21]), "=r"((r)[22]), "=r"((r)[23]), \
          "=r"((r)[24]), "=r"((r)[25]), "=r"((r)[26]), "=r"((r)[27]), \
          "=r"((r)[28]), "=r"((r)[29]), "=r"((r)[30]), "=r"((r)[31]) \
        : "r"(tm))

static constexpr uint64_t DESC_BASE_SW128 =
    (uint64_t(2) << 61) | (uint64_t(1) << 46) | (uint64_t(64) << 32) | (uint64_t(1) << 16);
#define MAKE_DESC(addr) (DESC_BASE_SW128 | ((uint64_t)((addr) >> 4) & 0x3FFF))

__device__ __forceinline__ void mma_f16_ss(uint32_t d, uint64_t ad, uint64_t bd,
                                           uint32_t idesc, uint32_t en) {
    asm volatile("{\n\t.reg .pred p;\n\tsetp.ne.u32 p, %5, 0;\n\t"
        "tcgen05.mma.cta_group::1.kind::f16 [%0], %1, %2, %3, {%4, %4, %4, %4}, p;\n\t}"
        :: "r"(d), "l"(ad), "l"(bd), "r"(idesc), "r"(0u), "r"(en) : "memory");
}
#else
__device__ __forceinline__ void mma16816(float* d, const uint32_t* a, const uint32_t* b) {
    asm volatile("mma.sync.aligned.m16n8k16.row.col.f32.bf16.bf16.f32 "
        "{%0,%1,%2,%3}, {%4,%5,%6,%7}, {%8,%9}, {%0,%1,%2,%3};"
        : "+f"(d[0]), "+f"(d[1]), "+f"(d[2]), "+f"(d[3])
        : "r"(a[0]), "r"(a[1]), "r"(a[2]), "r"(a[3]), "r"(b[0]), "r"(b[1]));
}
#endif

// ---------------------------------------------------------------------------
// bf16x3 GEMM:  C[M,N] = (A @ B^T) (+ bias) * alpha, split hi/lo operands.
// Tile 128x256, K-chunk 64, warp-specialized (256 loaders + 1 MMA warp).
// ---------------------------------------------------------------------------
#define BUFB 98304
#define GEMM_DSM (2 * BUFB + 1024)
#define GEMM_THREADS 288

__global__ __launch_bounds__(GEMM_THREADS) __cluster_dims__(1, 1, 1)
void gemm3(const __nv_bfloat16* __restrict__ Ah, const __nv_bfloat16* __restrict__ Al,
           const __nv_bfloat16* __restrict__ Bh, const __nv_bfloat16* __restrict__ Bl,
           const float* __restrict__ bias, float* __restrict__ C,
           int N, int K, float alpha)
{
    extern __shared__ char dsm[];

    const int tid = threadIdx.x;
    const int bm = blockIdx.y * 128;
    const int bn = blockIdx.x * 256;

    const uint32_t raw = smem_u32(dsm);
    const uint32_t sbase = (raw + 1023u) & ~1023u;
    char* sgen = dsm + (sbase - raw);

    const int NC = K / 64;

#if USE_TCGEN05
    __shared__ uint32_t s_tmem;
    __shared__ __align__(16) uint64_t s_full[2];
    __shared__ __align__(16) uint64_t s_empty[2];
    const uint32_t full0  = smem_u32(&s_full[0]),  full1  = smem_u32(&s_full[1]);
    const uint32_t empty0 = smem_u32(&s_empty[0]), empty1 = smem_u32(&s_empty[1]);

    if (tid < 32) { TCGEN05_ALLOC(smem_u32(&s_tmem), 256); TCGEN05_RELINQ(); }
    if (tid == 0) {
        MBARRIER_INIT(full0, 256);  MBARRIER_INIT(full1, 256);
        MBARRIER_INIT(empty0, 1);   MBARRIER_INIT(empty1, 1);
    }
    __syncthreads();
    const uint32_t tmem = s_tmem;

    if (tid < 256) {
        const int lr  = tid >> 3;
        const int seg = tid & 7;
        for (int c = 0; c < NC; c++) {
            if (c >= 2)
                MBARRIER_WAIT_PARITY((c & 1) ? empty1 : empty0, ((c - 2) >> 1) & 1);
            const uint32_t bb = sbase + (c & 1) * BUFB;
            const int k0 = c * 64;
#pragma unroll
            for (int t2 = 0; t2 < 2; t2++) {
                const __nv_bfloat16* basep = t2 ? Al : Ah;
                uint32_t tb = bb + t2 * 16384;
#pragma unroll
                for (int ii = 0; ii < 4; ii++) {
                    int r = lr + ii * 32;
                    const void* src = basep + (size_t)(bm + r) * K + k0 + seg * 8;
                    CP_ASYNC16(tb + SWZ((uint32_t)(r * 128 + seg * 16)), src);
                }
            }
#pragma unroll
            for (int t2 = 0; t2 < 2; t2++) {
                const __nv_bfloat16* basep = t2 ? Bl : Bh;
                uint32_t tb = bb + 32768 + t2 * 32768;
#pragma unroll
                for (int ii = 0; ii < 8; ii++) {
                    int r = lr + ii * 32;
                    const void* src = basep + (size_t)(bn + r) * K + k0 + seg * 8;
                    CP_ASYNC16(tb + SWZ((uint32_t)(r * 128 + seg * 16)), src);
                }
            }
            CP_ASYNC_MBAR_ARRIVE((c & 1) ? full1 : full0);
        }
    } else if (elect_one_pred()) {
        const uint32_t IDESC = (1u << 4) | (1u << 7) | (1u << 10) | (16u << 17) | (8u << 24);
        for (int c = 0; c < NC; c++) {
            MBARRIER_WAIT_PARITY((c & 1) ? full1 : full0, (c >> 1) & 1);
            FENCE_PROXY_ASYNC();
            const uint32_t ab = sbase + (c & 1) * BUFB;
            const uint64_t dAh  = MAKE_DESC(ab);
            const uint64_t dAl  = MAKE_DESC(ab + 16384);
            const uint64_t dBh0 = MAKE_DESC(ab + 32768);
            const uint64_t dBh1 = MAKE_DESC(ab + 32768 + 16384);
            const uint64_t dBl0 = MAKE_DESC(ab + 65536);
            const uint64_t dBl1 = MAKE_DESC(ab + 65536 + 16384);
            const uint32_t en0 = (c > 0);
#pragma unroll
            for (int ks = 0; ks < 4; ks++)
                mma_f16_ss(tmem,       dAh + ks * 2, dBh0 + ks * 2, IDESC, en0 || (ks > 0));
#pragma unroll
            for (int ks = 0; ks < 4; ks++)
                mma_f16_ss(tmem + 128, dAh + ks * 2, dBh1 + ks * 2, IDESC, en0 || (ks > 0));
#pragma unroll
            for (int ks = 0; ks < 4; ks++) {
                mma_f16_ss(tmem,       dAh + ks * 2, dBl0 + ks * 2, IDESC, 1u);
                mma_f16_ss(tmem + 128, dAh + ks * 2, dBl1 + ks * 2, IDESC, 1u);
                mma_f16_ss(tmem,       dAl + ks * 2, dBh0 + ks * 2, IDESC, 1u);
                mma_f16_ss(tmem + 128, dAl + ks * 2, dBh1 + ks * 2, IDESC, 1u);
            }
            TCGEN05_COMMIT((c & 1) ? empty1 : empty0);
        }
    }

    __syncthreads();
    MBARRIER_WAIT_PARITY(((NC - 1) & 1) ? empty1 : empty0, ((NC - 1) >> 1) & 1);
    TCGEN05_FENCE_AFTER();
    __syncthreads();

    float* stage = (float*)sgen;
    for (int slab = 0; slab < 8; slab++) {
        if (tid < 128) {
            uint32_t regs[32];
            TCGEN05_LD_X32(regs, tmem + slab * 32);
            TCGEN05_WAIT_LD();
#pragma unroll
            for (int cc = 0; cc < 32; cc++) stage[tid * 33 + cc] = __uint_as_float(regs[cc]);
        }
        __syncthreads();
        for (int e = tid; e < 4096; e += GEMM_THREADS) {
            int row = e >> 5, col = e & 31;
            float vv = stage[row * 33 + col] * alpha;
            if (bias) vv += bias[bn + slab * 32 + col];
            C[(size_t)(bm + row) * N + bn + slab * 32 + col] = vv;
        }
        __syncthreads();
    }
    if (tid < 32) TCGEN05_DEALLOC(tmem, 256);

#else  // HMMA fallback (generic pass; not selected on sm_103a hardware)
    const int warp = tid >> 5;
    const int lane = tid & 31;
    if (warp < 8) {
        const int wm = (warp & 3) * 32;
        const int wn = (warp >> 2) * 64;
        const int lg = lane >> 2;
        const int lt = lane & 3;
        const int lr  = tid >> 3;
        const int seg = tid & 7;

        auto load_chunk = [&](int c) {
            uint32_t bb = sbase + (c & 1) * BUFB;
            const int k0 = c * 64;
#pragma unroll
            for (int t2 = 0; t2 < 2; t2++) {
                const __nv_bfloat16* basep = t2 ? Al : Ah;
                uint32_t tb = bb + t2 * 16384;
#pragma unroll
                for (int ii = 0; ii < 4; ii++) {
                    int r = lr + ii * 32;
                    const void* src = basep + (size_t)(bm + r) * K + k0 + seg * 8;
                    CP_ASYNC16(tb + SWZ((uint32_t)(r * 128 + seg * 16)), src);
                }
            }
#pragma unroll
            for (int t2 = 0; t2 < 2; t2++) {
                const __nv_bfloat16* basep = t2 ? Bl : Bh;
                uint32_t tb = bb + 32768 + t2 * 32768;
#pragma unroll
                for (int ii = 0; ii < 8; ii++) {
                    int r = lr + ii * 32;
                    const void* src = basep + (size_t)(bn + r) * K + k0 + seg * 8;
                    CP_ASYNC16(tb + SWZ((uint32_t)(r * 128 + seg * 16)), src);
                }
            }
            CP_ASYNC_COMMIT();
        };

        for (int nh = 0; nh < 2; nh++) {
            float acc[2][8][4];
#pragma unroll
            for (int mt = 0; mt < 2; mt++)
#pragma unroll
                for (int nt = 0; nt < 8; nt++)
#pragma unroll
                    for (int r = 0; r < 4; r++) acc[mt][nt][r] = 0.f;

            load_chunk(0);
            for (int c = 0; c < NC; c++) {
                if (c + 1 < NC) { load_chunk(c + 1); CP_ASYNC_WAIT(1); }
                else            { CP_ASYNC_WAIT(0); }
                asm volatile("bar.sync 1, 256;" ::: "memory");

                char* bb = sgen + (c & 1) * BUFB;
                char* tAh = bb, *tAl = bb + 16384;
                char* tBh = bb + 32768 + nh * 16384, *tBl = bb + 65536 + nh * 16384;
#pragma unroll
                for (int kk = 0; kk < 64; kk += 16) {
                    const uint32_t kbase = (kk + lt * 2) * 2;
                    uint32_t bh[8][2], bl[8][2];
#pragma unroll
                    for (int nt = 0; nt < 8; nt++) {
                        uint32_t off = (uint32_t)((wn + nt * 8 + lg) * 128) + kbase;
                        bh[nt][0] = *(const uint32_t*)(tBh + SWZ(off));
                        bh[nt][1] = *(const uint32_t*)(tBh + SWZ(off + 16));
                        bl[nt][0] = *(const uint32_t*)(tBl + SWZ(off));
                        bl[nt][1] = *(const uint32_t*)(tBl + SWZ(off + 16));
                    }
#pragma unroll
                    for (int mt = 0; mt < 2; mt++) {
                        uint32_t o0 = (uint32_t)((wm + mt * 16 + lg) * 128) + kbase;
                        uint32_t o8 = o0 + 8 * 128;
                        uint32_t ah[4] = {
                            *(const uint32_t*)(tAh + SWZ(o0)),      *(const uint32_t*)(tAh + SWZ(o8)),
                            *(const uint32_t*)(tAh + SWZ(o0 + 16)), *(const uint32_t*)(tAh + SWZ(o8 + 16)) };
                        uint32_t al[4] = {
                            *(const uint32_t*)(tAl + SWZ(o0)),      *(const uint32_t*)(tAl + SWZ(o8)),
                            *(const uint32_t*)(tAl + SWZ(o0 + 16)), *(const uint32_t*)(tAl + SWZ(o8 + 16)) };
#pragma unroll
                        for (int nt = 0; nt < 8; nt++) mma16816(acc[mt][nt], ah, bh[nt]);
#pragma unroll
                        for (int nt = 0; nt < 8; nt++) mma16816(acc[mt][nt], ah, bl[nt]);
#pragma unroll
                        for (int nt = 0; nt < 8; nt++) mma16816(acc[mt][nt], al, bh[nt]);
                    }
                }
                asm volatile("bar.sync 1, 256;" ::: "memory");
            }
#pragma unroll
            for (int mt = 0; mt < 2; mt++) {
#pragma unroll
                for (int nt = 0; nt < 8; nt++) {
                    int row = bm + wm + mt * 16 + lg;
                    int col = bn + nh * 128 + wn + nt * 8 + lt * 2;
                    float b0 = bias ? bias[col]     : 0.f;
                    float b1 = bias ? bias[col + 1] : 0.f;
                    float2 v0 = { acc[mt][nt][0] * alpha + b0, acc[mt][nt][1] * alpha + b1 };
                    float2 v1 = { acc[mt][nt][2] * alpha + b0, acc[mt][nt][3] * alpha + b1 };
                    *(float2*)(C + (size_t)row * N + col)       = v0;
                    *(float2*)(C + (size_t)(row + 8) * N + col) = v1;
                }
            }
            asm volatile("bar.sync 1, 256;" ::: "memory");
        }
    }
#endif
}

// ---------------------------------------------------------------------------
// fp32 -> (hi, lo) bf16 split helpers
// ---------------------------------------------------------------------------
__device__ __forceinline__ void split4(const float4 v,
                                       __nv_bfloat16* hi, __nv_bfloat16* lo, int i)
{
    __nv_bfloat16 h0 = __float2bfloat16(v.x), h1 = __float2bfloat16(v.y);
    __nv_bfloat16 h2 = __float2bfloat16(v.z), h3 = __float2bfloat16(v.w);
    __nv_bfloat16 l0 = __float2bfloat16(v.x - __bfloat162float(h0));
    __nv_bfloat16 l1 = __float2bfloat16(v.y - __bfloat162float(h1));
    __nv_bfloat16 l2 = __float2bfloat16(v.z - __bfloat162float(h2));
    __nv_bfloat16 l3 = __float2bfloat16(v.w - __bfloat162float(h3));
    ushort4 ph = { __bfloat16_as_ushort(h0), __bfloat16_as_ushort(h1),
                   __bfloat16_as_ushort(h2), __bfloat16_as_ushort(h3) };
    ushort4 pl = { __bfloat16_as_ushort(l0), __bfloat16_as_ushort(l1),
                   __bfloat16_as_ushort(l2), __bfloat16_as_ushort(l3) };
    ((ushort4*)hi)[i] = ph;
    ((ushort4*)lo)[i] = pl;
}

// x split, 4 float4 per thread (MLP=4).  grid = MTOK*DMODEL/4/1024 = 2048.
__global__ __launch_bounds__(256)
void split32(const float* __restrict__ s, __nv_bfloat16* __restrict__ hi,
             __nv_bfloat16* __restrict__ lo)
{
    int base = blockIdx.x * 1024 + threadIdx.x;
    float4 v0 = ((const float4*)s)[base];
    float4 v1 = ((const float4*)s)[base + 256];
    float4 v2 = ((const float4*)s)[base + 512];
    float4 v3 = ((const float4*)s)[base + 768];
    split4(v0, hi, lo, base);
    split4(v1, hi, lo, base + 256);
    split4(v2, hi, lo, base + 512);
    split4(v3, hi, lo, base + 768);
}

// Weight splits into FUSED layouts. 4 float4/thread. 4096 blocks:
//  [0,512)    Wq  -> wqk rows 0..1023
//  [512,1024) Wk * SCALE_K -> wqk rows 1024..2047
//  [1024,2048) Wv -> wvg rows 0..2047
//  [2048,3072) Wg -> wvg rows 2048..4095
//  [3072,4096) Wo -> wo
__global__ __launch_bounds__(256)
void split_w(const float* __restrict__ Wq, const float* __restrict__ Wk,
             const float* __restrict__ Wv, const float* __restrict__ Wg,
             const float* __restrict__ Wo,
             __nv_bfloat16* __restrict__ wqkh, __nv_bfloat16* __restrict__ wqkl,
             __nv_bfloat16* __restrict__ wvgh, __nv_bfloat16* __restrict__ wvgl,
             __nv_bfloat16* __restrict__ woh,  __nv_bfloat16* __restrict__ wol)
{
    int b = blockIdx.x;
    const float* src; __nv_bfloat16 *hi, *lo; int dsto; float scale = 1.f;
    if      (b < 512)  { src = Wq; hi = wqkh; lo = wqkl; dsto = 0; }
    else if (b < 1024) { src = Wk; hi = wqkh; lo = wqkl; dsto = 1024 * 512; b -= 512; scale = SCALE_K; }
    else if (b < 2048) { src = Wv; hi = wvgh; lo = wvgl; dsto = 0; b -= 1024; }
    else if (b < 3072) { src = Wg; hi = wvgh; lo = wvgl; dsto = 2048 * 512; b -= 2048; }
    else               { src = Wo; hi = woh;  lo = wol;  dsto = 0; b -= 3072; }
    int base = b * 1024 + threadIdx.x;
#pragma unroll
    for (int u = 0; u < 4; u++) {
        int i = base + u * 256;
        float4 v = ((const float4*)src)[i];
        v.x *= scale; v.y *= scale; v.z *= scale; v.w *= scale;
        split4(v, hi, lo, dsto + i);
    }
}

// W_eff = Wkg2 @ Wkg1 -> wqk rows 2048..3071 (fused), hi/lo split.
__global__ __launch_bounds__(256)
void weff_split(const float* __restrict__ W1, const float* __restrict__ W2,
                __nv_bfloat16* __restrict__ wqkh, __nv_bfloat16* __restrict__ wqkl)
{
    __shared__ __align__(16) float s1[16][128];
    const int tid = threadIdx.x;
    const int d0  = blockIdx.x * 128;
    const int n0  = blockIdx.y * 256;

#pragma unroll
    for (int it = 0; it < 2; it++) {
        int i = it * 256 + tid;
        int r = i >> 5, c4 = i & 31;
        *(float4*)&s1[r][c4 * 4] = *(const float4*)(W1 + r * DMODEL + d0 + c4 * 4);
    }
    __syncthreads();

    const int d4 = tid & 31;
    const int nb = tid >> 5;
    for (int n = n0 + nb; n < n0 + 256; n += 8) {
        const float4 w2a = *(const float4*)(W2 + n * 16);
        const float4 w2b = *(const float4*)(W2 + n * 16 + 4);
        const float4 w2c = *(const float4*)(W2 + n * 16 + 8);
        const float4 w2d = *(const float4*)(W2 + n * 16 + 12);
        float w2[16] = { w2a.x, w2a.y, w2a.z, w2a.w, w2b.x, w2b.y, w2b.z, w2b.w,
                         w2c.x, w2c.y, w2c.z, w2c.w, w2d.x, w2d.y, w2d.z, w2d.w };
        float4 acc = {0.f, 0.f, 0.f, 0.f};
#pragma unroll
        for (int r = 0; r < 16; r++) {
            float4 v = *(const float4*)&s1[r][d4 * 4];
            acc.x = fmaf(w2[r], v.x, acc.x);
            acc.y = fmaf(w2[r], v.y, acc.y);
            acc.z = fmaf(w2[r], v.z, acc.z);
            acc.w = fmaf(w2[r], v.w, acc.w);
        }
        split4(acc, wqkh, wqkl, (2048 + n) * 512 + (d0 >> 2) + d4);
    }
}

// fused bias vectors: bqkg = [0 | 0 | bkg2], bvg = [0 | bg]
__global__ void fill_bias(const float* __restrict__ bkg2, const float* __restrict__ bg,
                          float* __restrict__ bqkg, float* __restrict__ bvg)
{
    int i = blockIdx.x * 256 + threadIdx.x;
    if (i < QS) bqkg[i] = (i >= 2048) ? bkg2[i - 2048] : 0.f;
    if (i < VS) bvg [i] = (i >= 2048) ? bg  [i - 2048] : 0.f;
}

// ===========================================================================
// CHUNKED GLA SCAN (exact algebra; fp32).  Chunk length CH=64.
// ===========================================================================

// ---------- Phase A -----------------------------------------------------------
#define PHA_SMEM (16384 * 4)
__global__ __launch_bounds__(256)
void gla_pha(const float* __restrict__ k, const float* __restrict__ kg,
             const float* __restrict__ v, float* __restrict__ a_g,
             float* __restrict__ U_g)
{
    extern __shared__ float sa[];
    float* lam = sa;                 // [64][64]
    float* kh  = sa + 4096;          // [64][64]
    float* vsm = sa + 8192;          // [64][128]

    const int blk = blockIdx.x;
    const int c   = blk & (NCK - 1);
    const int bh  = blk >> 5;
    const int b   = bh >> 4, h = bh & 15;
    const int t0  = c * CH;
    const int tid = threadIdx.x;

    const float* kb = k  + (size_t)b * SEQ * QS + h * DK;
    const float* gb = kg + (size_t)b * SEQ * QS + h * DK;
    const float* vb = v  + (size_t)b * SEQ * VS + h * DV;
    float* ag = a_g + ((size_t)bh * SEQ + t0) * DK;
    float* Ug = U_g + (size_t)blk * (DK * DV);

    for (int e = tid; e < CH * DK; e += 256) {
        int t = e >> 6, i = e & 63;
        float x = gb[(size_t)(t0 + t) * QS + i];
        float ls = fminf(x, 0.f) - log1pf(__expf(-fabsf(x)));
        lam[t * DK + i] = __expf(ls * INV_NORM);
    }
    for (int e = tid; e < CH * (DV / 4); e += 256) {
        int t = e >> 5, j4 = e & 31;
        *(float4*)&vsm[t * DV + j4 * 4] =
            *(const float4*)&vb[(size_t)(t0 + t) * VS + j4 * 4];
    }
    __syncthreads();

    if (tid < DK) {
        const int i = tid;
        float acc = 1.f;
        for (int t = 0; t < CH; t++) {
            acc *= lam[t * DK + i];
            ag[(size_t)t * DK + i] = acc;
        }
        float w = 1.f;
        for (int t = CH - 1; t >= 0; t--) {
            kh[t * DK + i] = kb[(size_t)(t0 + t) * QS + i] * w;
            w *= lam[t * DK + i];
        }
    }
    __syncthreads();

    {
        const int i0 = (tid >> 5) * 8;
        const int j0 = (tid & 31) * 4;
        float acc[8][4];
#pragma unroll
        for (int ii = 0; ii < 8; ii++)
#pragma unroll
            for (int jj = 0; jj < 4; jj++) acc[ii][jj] = 0.f;

        for (int s = 0; s < CH; s++) {
            float4 va = *(const float4*)&vsm[s * DV + j0];
            float kv[8];
            *(float4*)&kv[0] = *(const float4*)&kh[s * DK + i0];
            *(float4*)&kv[4] = *(const float4*)&kh[s * DK + i0 + 4];
#pragma unroll
            for (int ii = 0; ii < 8; ii++) {
                acc[ii][0] = fmaf(kv[ii], va.x, acc[ii][0]);
                acc[ii][1] = fmaf(kv[ii], va.y, acc[ii][1]);
                acc[ii][2] = fmaf(kv[ii], va.z, acc[ii][2]);
                acc[ii][3] = fmaf(kv[ii], va.w, acc[ii][3]);
            }
        }
#pragma unroll
        for (int ii = 0; ii < 8; ii++) {
            float4 w4 = { acc[ii][0], acc[ii][1], acc[ii][2], acc[ii][3] };
            *(float4*)&Ug[(size_t)(i0 + ii) * DV + j0] = w4;
        }
    }
}

// ---------- Phase B ----------------------------------------------------------
__global__ __launch_bounds__(256)
void gla_phb(const float* __restrict__ a_g, const float* __restrict__ U_g,
             float* __restrict__ Sp_g)
{
    const int bh  = blockIdx.x;
    const int tid = threadIdx.x;
    float S[32];
#pragma unroll
    for (int w = 0; w < 32; w++) S[w] = 0.f;

    for (int c = 0; c < NCK; c++) {
        const float* Ug = U_g + ((size_t)bh * NCK + c) * (DK * DV);
        float* Sg = Sp_g + ((size_t)bh * NCK + c) * (DK * DV);
        const float* a64 = a_g + ((size_t)bh * SEQ + c * CH + CH - 1) * DK;
#pragma unroll
        for (int w = 0; w < 8; w++) {
            int f4 = tid + w * 256;
            int i = f4 >> 5;
            float ai = a64[i];
            float4 u = ((const float4*)Ug)[f4];
            float4 s = *(float4*)&S[w * 4];
            ((float4*)Sg)[f4] = s;
            s.x = fmaf(s.x, ai, u.x);
            s.y = fmaf(s.y, ai, u.y);
            s.z = fmaf(s.z, ai, u.z);
            s.w = fmaf(s.w, ai, u.w);
            *(float4*)&S[w * 4] = s;
        }
    }
}

// ---------- Phase C (register-tiled) -----------------------------------------
#define PHC_SMEM (29248 * 4)
__global__ __launch_bounds__(256)
void gla_phc(const float* __restrict__ q, const float* __restrict__ a_g,
             const float* __restrict__ k, const float* __restrict__ Sp_g,
             const float* __restrict__ v, float* __restrict__ o)
{
    extern __shared__ float sc[];
    float* qt  = sc;            // [64][68]
    float* kT  = sc + 4352;     // [64(i)][68(s)]
    float* Am  = sc + 8704;     // [64][65]
    float* vsm = sc + 12864;    // [64][128]
    float* Ssm = sc + 21056;    // [64][128]

    const int blk = blockIdx.x;
    const int c   = blk & (NCK - 1);
    const int bh  = blk >> 5;
    const int b   = bh >> 4, h = bh & 15;
    const int t0  = c * CH;
    const int tid = threadIdx.x;

    const float* qb = q + (size_t)b * SEQ * QS + h * DK;
    const float* kb = k + (size_t)b * SEQ * QS + h * DK;
    const float* vb = v + (size_t)b * SEQ * VS + h * DV;
    const float* ag = a_g + ((size_t)bh * SEQ + t0) * DK;
    const float* Sg = Sp_g + (size_t)blk * (DK * DV);
    float* ob = o + (size_t)b * SEQ * DMODEL + h * DV;

    for (int e = tid; e < CH * DK; e += 256) {
        int t = e >> 6, i = e & 63;
        float aa = ag[(size_t)t * DK + i];
        qt[t * 68 + i] = qb[(size_t)(t0 + t) * QS + i] * aa;
        kT[i * 68 + t] = kb[(size_t)(t0 + t) * QS + i] / aa;
    }
    for (int e = tid; e < CH * (DV / 4); e += 256) {
        int t = e >> 5, j4 = e & 31;
        *(float4*)&vsm[t * DV + j4 * 4] =
            *(const float4*)&vb[(size_t)(t0 + t) * VS + j4 * 4];
        *(float4*)&Ssm[t * DV + j4 * 4] = ((const float4*)Sg)[e];
    }
    __syncthreads();

    // A = tril(qt @ kT): thread owns 2 t x 8 s
    {
        const int ta = (tid >> 3) * 2;
        const int s0 = (tid & 7) * 8;
        float acc0[8], acc1[8];
#pragma unroll
        for (int ss = 0; ss < 8; ss++) { acc0[ss] = 0.f; acc1[ss] = 0.f; }
        for (int i = 0; i < DK; i++) {
            float q0 = qt[ta * 68 + i];
            float q1 = qt[(ta + 1) * 68 + i];
            const float* kr = &kT[i * 68 + s0];
            float4 k0 = *(const float4*)&kr[0];
            float4 k1 = *(const float4*)&kr[4];
            float kv[8] = { k0.x, k0.y, k0.z, k0.w, k1.x, k1.y, k1.z, k1.w };
#pragma unroll
            for (int ss = 0; ss < 8; ss++) {
                acc0[ss] = fmaf(q0, kv[ss], acc0[ss]);
                acc1[ss] = fmaf(q1, kv[ss], acc1[ss]);
            }
        }
#pragma unroll
        for (int ss = 0; ss < 8; ss++) {
            int s = s0 + ss;
            Am[ta * 65 + s]       = (s <= ta)     ? acc0[ss] : 0.f;
            Am[(ta + 1) * 65 + s] = (s <= ta + 1) ? acc1[ss] : 0.f;
        }
    }
    __syncthreads();

    // o = A@V + qt@S_pre : thread owns 4 t x 8 j
    {
        const int to = (tid >> 4) * 4;
        const int j0 = (tid & 15) * 8;
        float acc[4][8];
#pragma unroll
        for (int r = 0; r < 4; r++)
#pragma unroll
            for (int jj = 0; jj < 8; jj++) acc[r][jj] = 0.f;

        const int smax = to + 4;           // tril: rows to..to+3 need s<=t; Am=0 above diag
        for (int s = 0; s < smax; s++) {
            float a0 = Am[to * 65 + s];
            float a1 = Am[(to + 1) * 65 + s];
            float a2 = Am[(to + 2) * 65 + s];
            float a3 = Am[(to + 3) * 65 + s];
            const float* vr = &vsm[s * DV + j0];
            float4 v0 = *(const float4*)&vr[0];
            float4 v1 = *(const float4*)&vr[4];
            float vv[8] = { v0.x, v0.y, v0.z, v0.w, v1.x, v1.y, v1.z, v1.w };
#pragma unroll
            for (int jj = 0; jj < 8; jj++) {
                acc[0][jj] = fmaf(a0, vv[jj], acc[0][jj]);
                acc[1][jj] = fmaf(a1, vv[jj], acc[1][jj]);
                acc[2][jj] = fmaf(a2, vv[jj], acc[2][jj]);
                acc[3][jj] = fmaf(a3, vv[jj], acc[3][jj]);
            }
        }
        for (int i = 0; i < DK; i++) {
            float q0 = qt[to * 68 + i];
            float q1 = qt[(to + 1) * 68 + i];
            float q2 = qt[(to + 2) * 68 + i];
            float q3 = qt[(to + 3) * 68 + i];
            const float* sr = &Ssm[i * DV + j0];
            float4 s0v = *(const float4*)&sr[0];
            float4 s1v = *(const float4*)&sr[4];
            float sv[8] = { s0v.x, s0v.y, s0v.z, s0v.w, s1v.x, s1v.y, s1v.z, s1v.w };
#pragma unroll
            for (int jj = 0; jj < 8; jj++) {
                acc[0][jj] = fmaf(q0, sv[jj], acc[0][jj]);
                acc[1][jj] = fmaf(q1, sv[jj], acc[1][jj]);
                acc[2][jj] = fmaf(q2, sv[jj], acc[2][jj]);
                acc[3][jj] = fmaf(q3, sv[jj], acc[3][jj]);
            }
        }
#pragma unroll
        for (int r = 0; r < 4; r++) {
            float* orow = ob + (size_t)(t0 + to + r) * DMODEL + j0;
            float4 w0 = { acc[r][0], acc[r][1], acc[r][2], acc[r][3] };
            float4 w1 = { acc[r][4], acc[r][5], acc[r][6], acc[r][7] };
            *(float4*)&orow[0] = w0;
            *(float4*)&orow[4] = w1;
        }
    }
}

// ---------------------------------------------------------------------------
// LayerNorm(dv=128, no affine) + SiLU(gp) gate, fused hi/lo bf16 split.
// gp lives in the fused vg buffer at row stride VS, column offset handled by
// caller (gp = vg + 2048).
// ---------------------------------------------------------------------------
__global__ __launch_bounds__(256)
void ln_gate(const float* __restrict__ o, const float* __restrict__ gp,
             __nv_bfloat16* __restrict__ zh, __nv_bfloat16* __restrict__ zl)
{
    int gw   = (blockIdx.x * blockDim.x + threadIdx.x) >> 5;   // 65536 rows
    int lane = threadIdx.x & 31;
    int m = gw >> 4, h = gw & 15;

    float4 ov = ((const float4*)(o + (size_t)gw * 128))[lane];
    float s = ov.x + ov.y + ov.z + ov.w;
#pragma unroll
    for (int d = 16; d > 0; d >>= 1) s += __shfl_xor_sync(0xffffffffu, s, d);
    float mu = s * (1.f / 128.f);

    float dx0 = ov.x - mu, dx1 = ov.y - mu, dx2 = ov.z - mu, dx3 = ov.w - mu;
    float vsum = dx0 * dx0 + dx1 * dx1 + dx2 * dx2 + dx3 * dx3;
#pragma unroll
    for (int d = 16; d > 0; d >>= 1) vsum += __shfl_xor_sync(0xffffffffu, vsum, d);
    float inv = rsqrtf(vsum * (1.f / 128.f) + 1e-5f);

    float4 gv = ((const float4*)(gp + (size_t)m * VS + (h << 7)))[lane];
    float4 z;
    z.x = (gv.x / (1.f + __expf(-gv.x))) * (dx0 * inv);
    z.y = (gv.y / (1.f + __expf(-gv.y))) * (dx1 * inv);
    z.z = (gv.z / (1.f + __expf(-gv.z))) * (dx2 * inv);
    z.w = (gv.w / (1.f + __expf(-gv.w))) * (dx3 * inv);
    split4(z, zh, zl, gw * 32 + lane);
}

// ---------------------------------------------------------------------------
extern "C" void kernel_launch(void* const* d_in, const int* in_sizes, int n_in,
                              void* d_out, int out_size)
{
    const float* x    = (const float*)d_in[0];
    const float* Wq   = (const float*)d_in[1];
    const float* Wk   = (const float*)d_in[2];
    const float* Wkg1 = (const float*)d_in[3];
    const float* Wkg2 = (const float*)d_in[4];
    const float* bkg2 = (const float*)d_in[5];
    const float* Wv   = (const float*)d_in[6];
    const float* Wg   = (const float*)d_in[7];
    const float* bg   = (const float*)d_in[8];
    const float* Wo   = (const float*)d_in[9];
    float* out = (float*)d_out;

    float *qkg, *vg, *o, *ad, *Ud, *Sp, *bqkg, *bvg;
    cudaGetSymbolAddress((void**)&qkg,  g_qkg);
    cudaGetSymbolAddress((void**)&vg,   g_vg);
    cudaGetSymbolAddress((void**)&o,    g_o);
    cudaGetSymbolAddress((void**)&ad,   g_a);
    cudaGetSymbolAddress((void**)&Ud,   g_U);
    cudaGetSymbolAddress((void**)&Sp,   g_Sp);
    cudaGetSymbolAddress((void**)&bqkg, g_bqkg);
    cudaGetSymbolAddress((void**)&bvg,  g_bvg);

    __nv_bfloat16 *xh, *xl, *zh, *zl;
    __nv_bfloat16 *wqkh, *wqkl, *wvgh, *wvgl, *woh, *wol;
    cudaGetSymbolAddress((void**)&xh,   g_xh);   cudaGetSymbolAddress((void**)&xl,   g_xl);
    cudaGetSymbolAddress((void**)&zh,   g_zh);   cudaGetSymbolAddress((void**)&zl,   g_zl);
    cudaGetSymbolAddress((void**)&wqkh, g_wqkh); cudaGetSymbolAddress((void**)&wqkl, g_wqkl);
    cudaGetSymbolAddress((void**)&wvgh, g_wvgh); cudaGetSymbolAddress((void**)&wvgl, g_wvgl);
    cudaGetSymbolAddress((void**)&woh,  g_woh);  cudaGetSymbolAddress((void**)&wol,  g_wol);

    cudaFuncSetAttribute(gemm3, cudaFuncAttributeMaxDynamicSharedMemorySize, GEMM_DSM);
    cudaFuncSetAttribute(gla_pha, cudaFuncAttributeMaxDynamicSharedMemorySize, PHA_SMEM);
    cudaFuncSetAttribute(gla_phc, cudaFuncAttributeMaxDynamicSharedMemorySize, PHC_SMEM);

    // splits + fused low-rank weight + fused biases
    split32<<<(MTOK * DMODEL) / 4096, 256>>>(x, xh, xl);
    split_w<<<4096, 256>>>(Wq, Wk, Wv, Wg, Wo, wqkh, wqkl, wvgh, wvgl, woh, wol);
    weff_split<<<dim3(16, 4), 256>>>(Wkg1, Wkg2, wqkh, wqkl);
    fill_bias<<<16, 256>>>(bkg2, bg, bqkg, bvg);

    dim3 blk(GEMM_THREADS);
    dim3 gQKG(QS / 256, MTOK / 128);     // 12 x 32
    dim3 gVG (VS / 256, MTOK / 128);     // 16 x 32
    dim3 gOUT(DMODEL / 256, MTOK / 128); // 8 x 32

    gemm3<<<gQKG, blk, GEMM_DSM>>>(xh, xl, wqkh, wqkl, bqkg, qkg, QS, DMODEL, 1.f);
    gemm3<<<gVG,  blk, GEMM_DSM>>>(xh, xl, wvgh, wvgl, bvg,  vg,  VS, DMODEL, 1.f);

    // chunked scan (q = qkg+0, k = qkg+1024, kg = qkg+2048; v = vg+0)
    gla_pha<<<BH * NCK, 256, PHA_SMEM>>>(qkg + 1024, qkg + 2048, vg, ad, Ud);
    gla_phb<<<BH, 256>>>(ad, Ud, Sp);
    gla_phc<<<BH * NCK, 256, PHC_SMEM>>>(qkg, ad, qkg + 1024, Sp, vg, o);

    ln_gate<<<(MTOK * NHEAD * 32) / 256, 256>>>(o, vg + 2048, zh, zl);

    gemm3<<<gOUT, blk, GEMM_DSM>>>(zh, zl, woh, wol, nullptr, out, DMODEL, DMODEL, 1.f);
}